// round 15
// baseline (speedup 1.0000x reference)
#include <cuda_runtime.h>
#include <math.h>
#include <stdint.h>

// ---------------- problem constants ----------------
constexpr int NN   = 20000;
constexpr int EE   = 320000;
constexpr int NT   = 200000;
constexpr int DC   = 256;

// ---------------- scratch (static device globals; no runtime alloc) --------
__device__ float g_W12t[512 * 512];        // transposed fused weights [n][k]
__device__ float g_b12[512];
__device__ float g_lint[128 * 256];        // lin_W^T
__device__ float g_tftgt[256 * 256];       // [tf_W | tg_W]^T
__device__ float g_btftg[256];
__device__ float g_Wqt[128 * 128];
__device__ float g_Woabt[128 * 128];       // (Wo @ [tfa_W|tga_W])^T
__device__ float g_bab2[128];              // bo@Wab + [tfa_b|tga_b]

__device__ float g_h[(size_t)NN * 512];    // [h_gcn1 | h_gcn2]
__device__ float g_dinv[NN];

__device__ int g_deg[NN];
__device__ int g_cnt[NN];
__device__ int g_off[NN + 1];
__device__ int g_esrc[EE];

__device__ float g_g1[(size_t)NN * 256];
__device__ float g_xa[(size_t)NN * 256];
__device__ float g_xg[(size_t)NN * 128];
__device__ float g_tftg[(size_t)NN * 256];

__device__ float g_kin[(size_t)NN * 128];
__device__ float g_q[(size_t)NN * 128];
__device__ float g_peq[512 * 128];

__device__ float g_kinc[DC * 128];
__device__ float g_vinc[DC * 128];
__device__ float g_rsk[DC];
__device__ float g_rsv[DC];
__device__ float g_kc[DC * 128];
__device__ float g_vc[DC * 128];

__device__ float g_att[(size_t)NN * 128];
__device__ float g_ab[(size_t)NN * 128];
__device__ float g_na[NN];
__device__ float g_nb[NN];

// ---------------- tf32 helpers ----------------
__device__ __forceinline__ uint32_t cvt_tf32(float f) {
    uint32_t u;
    asm("cvt.rna.tf32.f32 %0, %1;" : "=r"(u) : "f"(f));
    return u;
}
__device__ __forceinline__ uint4 cvt_tf32x4(float4 v) {
    uint4 r;
    r.x = cvt_tf32(v.x); r.y = cvt_tf32(v.y);
    r.z = cvt_tf32(v.z); r.w = cvt_tf32(v.w);
    return r;
}
// hi/lo split for 3xTF32
__device__ __forceinline__ void split_tf32x4(float4 v, uint4& hi, uint4& lo) {
    hi = cvt_tf32x4(v);
    lo.x = cvt_tf32(v.x - __uint_as_float(hi.x));
    lo.y = cvt_tf32(v.y - __uint_as_float(hi.y));
    lo.z = cvt_tf32(v.z - __uint_as_float(hi.z));
    lo.w = cvt_tf32(v.w - __uint_as_float(hi.w));
}
#define MMA_TF32(c, a, b) \
    asm volatile( \
        "mma.sync.aligned.m16n8k8.row.col.f32.tf32.tf32.f32 " \
        "{%0,%1,%2,%3}, {%4,%5,%6,%7}, {%8,%9}, {%0,%1,%2,%3};" \
        : "+f"((c)[0]), "+f"((c)[1]), "+f"((c)[2]), "+f"((c)[3]) \
        : "r"((a)[0]), "r"((a)[1]), "r"((a)[2]), "r"((a)[3]), \
          "r"((b)[0]), "r"((b)[1]))

// ---------------- generic tf32 mma.sync GEMM: C = act(A@Bt^T + bias) -------
// BM=128, BN=128, BK=32. 256 threads = 8 warps; warp tile 64x32 (4x4 m16n8k8).
// ACT: 0 = none, 1 = leaky relu. KIN: also write g_kin for cols<128.
constexpr int SPAD = 36;
template <int ACT, int KIN>
__global__ void __launch_bounds__(256)
mma_gemm(const float* __restrict__ A, const float* __restrict__ Bt,
         const float* __restrict__ bias, float* __restrict__ C,
         int M, int N, int K,
         const int* __restrict__ positions, const float* __restrict__ pos_emb) {
    __shared__ uint32_t sA[128 * SPAD];
    __shared__ uint32_t sB[128 * SPAD];
    const int tid = threadIdx.x;
    const int lane = tid & 31, wid = tid >> 5;
    const int wr = wid >> 2, wc = wid & 3;
    const int gq = lane >> 2, tq = lane & 3;
    const int rowBase = blockIdx.y * 128;
    const int colBase = blockIdx.x * 128;

    float c[4][4][4];
#pragma unroll
    for (int mt = 0; mt < 4; mt++)
#pragma unroll
        for (int nt = 0; nt < 4; nt++)
#pragma unroll
            for (int r = 0; r < 4; r++) c[mt][nt][r] = 0.0f;

    int lrow[4], lc4[4];
#pragma unroll
    for (int p = 0; p < 4; p++) {
        int idx = tid + p * 256;
        lrow[p] = idx >> 3;
        lc4[p] = idx & 7;
    }

    uint4 ra[4], rb[4];
#pragma unroll
    for (int p = 0; p < 4; p++) {
        int arow = rowBase + lrow[p];
        float4 av = (arow < M)
            ? *(const float4*)(A + (size_t)arow * K + lc4[p] * 4)
            : make_float4(0.f, 0.f, 0.f, 0.f);
        ra[p] = cvt_tf32x4(av);
        float4 bv = *(const float4*)(Bt + (size_t)(colBase + lrow[p]) * K + lc4[p] * 4);
        rb[p] = cvt_tf32x4(bv);
    }
#pragma unroll
    for (int p = 0; p < 4; p++) {
        *(uint4*)&sA[lrow[p] * SPAD + lc4[p] * 4] = ra[p];
        *(uint4*)&sB[lrow[p] * SPAD + lc4[p] * 4] = rb[p];
    }
    __syncthreads();

    const int niter = K >> 5;
    for (int it = 0; it < niter; it++) {
        if (it + 1 < niter) {
            const int k0 = (it + 1) * 32;
#pragma unroll
            for (int p = 0; p < 4; p++) {
                int arow = rowBase + lrow[p];
                float4 av = (arow < M)
                    ? *(const float4*)(A + (size_t)arow * K + k0 + lc4[p] * 4)
                    : make_float4(0.f, 0.f, 0.f, 0.f);
                ra[p] = cvt_tf32x4(av);
                float4 bv = *(const float4*)(Bt + (size_t)(colBase + lrow[p]) * K + k0 + lc4[p] * 4);
                rb[p] = cvt_tf32x4(bv);
            }
        }
#pragma unroll
        for (int ks = 0; ks < 4; ks++) {
            const int kb = ks * 8 + tq;
            uint32_t af[4][4];
#pragma unroll
            for (int mt = 0; mt < 4; mt++) {
                int base = (wr * 64 + mt * 16 + gq) * SPAD + kb;
                af[mt][0] = sA[base];
                af[mt][1] = sA[base + 8 * SPAD];
                af[mt][2] = sA[base + 4];
                af[mt][3] = sA[base + 8 * SPAD + 4];
            }
            uint32_t bf[4][2];
#pragma unroll
            for (int nt = 0; nt < 4; nt++) {
                int base = (wc * 32 + nt * 8 + gq) * SPAD + kb;
                bf[nt][0] = sB[base];
                bf[nt][1] = sB[base + 4];
            }
#pragma unroll
            for (int mt = 0; mt < 4; mt++)
#pragma unroll
                for (int nt = 0; nt < 4; nt++)
                    MMA_TF32(c[mt][nt], af[mt], bf[nt]);
        }
        __syncthreads();
        if (it + 1 < niter) {
#pragma unroll
            for (int p = 0; p < 4; p++) {
                *(uint4*)&sA[lrow[p] * SPAD + lc4[p] * 4] = ra[p];
                *(uint4*)&sB[lrow[p] * SPAD + lc4[p] * 4] = rb[p];
            }
            __syncthreads();
        }
    }

#pragma unroll
    for (int mt = 0; mt < 4; mt++) {
        int row0 = rowBase + wr * 64 + mt * 16 + gq;
#pragma unroll
        for (int nt = 0; nt < 4; nt++) {
            int col = colBase + wc * 32 + nt * 8 + tq * 2;
            float b0 = 0.f, b1 = 0.f;
            if (bias) {
                float2 bb = *(const float2*)(bias + col);
                b0 = bb.x; b1 = bb.y;
            }
            float v0 = c[mt][nt][0] + b0, v1 = c[mt][nt][1] + b1;
            float v2 = c[mt][nt][2] + b0, v3 = c[mt][nt][3] + b1;
            if (ACT == 1) {
                v0 = (v0 >= 0.f) ? v0 : 0.01f * v0;
                v1 = (v1 >= 0.f) ? v1 : 0.01f * v1;
                v2 = (v2 >= 0.f) ? v2 : 0.01f * v2;
                v3 = (v3 >= 0.f) ? v3 : 0.01f * v3;
            }
            if (row0 < M) {
                float2 o = { v0, v1 };
                *(float2*)(C + (size_t)row0 * N + col) = o;
                if (KIN && col < 128) {
                    float2 pe = *(const float2*)(pos_emb + (size_t)positions[row0] * 128 + col);
                    float2 kk = { v0 + pe.x, v1 + pe.y };
                    *(float2*)(g_kin + (size_t)row0 * 128 + col) = kk;
                }
            }
            if (row0 + 8 < M) {
                float2 o = { v2, v3 };
                *(float2*)(C + (size_t)(row0 + 8) * N + col) = o;
                if (KIN && col < 128) {
                    float2 pe = *(const float2*)(pos_emb + (size_t)positions[row0 + 8] * 128 + col);
                    float2 kk = { v2 + pe.x, v3 + pe.y };
                    *(float2*)(g_kin + (size_t)(row0 + 8) * 128 + col) = kk;
                }
            }
        }
    }
}

// ---------------- split-K 3xTF32 mma: kinc = Ek@kin, vinc = Ev@tg ----------
// 3xTF32 (hi/lo split, drop lo*lo) restores ~fp32 product accuracy.
// tile 128(M) x 128(N) x 16(K-chunk); grid (1, 2, 2*NSPLIT); CH chunks/split.
constexpr int SPAD2 = 20;
constexpr int NSPLIT = 125;
constexpr int CH_PER_SPLIT = 10;   // 125*10*16 = 20000
__global__ void __launch_bounds__(256)
splitk_mma(const float* __restrict__ Ekm, const float* __restrict__ Evm) {
    __shared__ uint32_t sAh[128 * SPAD2];
    __shared__ uint32_t sAl[128 * SPAD2];
    __shared__ uint32_t sBh[128 * SPAD2];
    __shared__ uint32_t sBl[128 * SPAD2];
    const int mat = blockIdx.z & 1;
    const int split = blockIdx.z >> 1;
    const float* Am = mat ? Evm : Ekm;
    const float* Xm = mat ? (g_tftg + 128) : g_kin;
    const int ldb = mat ? 256 : 128;
    float* Cm = mat ? g_vinc : g_kinc;
    const int rowBase = blockIdx.y * 128;

    const int tid = threadIdx.x;
    const int lane = tid & 31, wid = tid >> 5;
    const int wr = wid >> 2, wc = wid & 3;
    const int gq = lane >> 2, tq = lane & 3;

    float c[4][4][4];
#pragma unroll
    for (int mt = 0; mt < 4; mt++)
#pragma unroll
        for (int nt = 0; nt < 4; nt++)
#pragma unroll
            for (int r = 0; r < 4; r++) c[mt][nt][r] = 0.0f;

    // BK=16: A tile 128x16 = 512 float4 (2/thread); B tile 16x128 = 512 float4.
    int lrow[2], lc4[2], bkk[2], bn0[2];
#pragma unroll
    for (int p = 0; p < 2; p++) {
        int idx = tid + p * 256;
        lrow[p] = idx >> 2;        // A row 0..127
        lc4[p] = idx & 3;          // A k-float4 0..3
        bkk[p] = idx >> 5;         // B k-row 0..15
        bn0[p] = (idx & 31) * 4;   // B n 0..124
    }

    const int kstart = split * CH_PER_SPLIT * 16;
    uint4 rah[2], ral[2], rbh[2], rbl[2];
    // preload chunk 0
#pragma unroll
    for (int p = 0; p < 2; p++) {
        float4 av = *(const float4*)(Am + (size_t)(rowBase + lrow[p]) * NN + kstart + lc4[p] * 4);
        split_tf32x4(av, rah[p], ral[p]);
        float4 bv = *(const float4*)(Xm + (size_t)(kstart + bkk[p]) * ldb + bn0[p]);
        split_tf32x4(bv, rbh[p], rbl[p]);
    }
#pragma unroll
    for (int p = 0; p < 2; p++) {
        *(uint4*)&sAh[lrow[p] * SPAD2 + lc4[p] * 4] = rah[p];
        *(uint4*)&sAl[lrow[p] * SPAD2 + lc4[p] * 4] = ral[p];
        sBh[(bn0[p] + 0) * SPAD2 + bkk[p]] = rbh[p].x;
        sBh[(bn0[p] + 1) * SPAD2 + bkk[p]] = rbh[p].y;
        sBh[(bn0[p] + 2) * SPAD2 + bkk[p]] = rbh[p].z;
        sBh[(bn0[p] + 3) * SPAD2 + bkk[p]] = rbh[p].w;
        sBl[(bn0[p] + 0) * SPAD2 + bkk[p]] = rbl[p].x;
        sBl[(bn0[p] + 1) * SPAD2 + bkk[p]] = rbl[p].y;
        sBl[(bn0[p] + 2) * SPAD2 + bkk[p]] = rbl[p].z;
        sBl[(bn0[p] + 3) * SPAD2 + bkk[p]] = rbl[p].w;
    }
    __syncthreads();

    for (int it = 0; it < CH_PER_SPLIT; it++) {
        if (it + 1 < CH_PER_SPLIT) {
            const int k0 = kstart + (it + 1) * 16;
#pragma unroll
            for (int p = 0; p < 2; p++) {
                float4 av = *(const float4*)(Am + (size_t)(rowBase + lrow[p]) * NN + k0 + lc4[p] * 4);
                split_tf32x4(av, rah[p], ral[p]);
                float4 bv = *(const float4*)(Xm + (size_t)(k0 + bkk[p]) * ldb + bn0[p]);
                split_tf32x4(bv, rbh[p], rbl[p]);
            }
        }
#pragma unroll
        for (int ks = 0; ks < 2; ks++) {
            const int kb = ks * 8 + tq;
            uint32_t afh[4][4], afl[4][4];
#pragma unroll
            for (int mt = 0; mt < 4; mt++) {
                int base = (wr * 64 + mt * 16 + gq) * SPAD2 + kb;
                afh[mt][0] = sAh[base];
                afh[mt][1] = sAh[base + 8 * SPAD2];
                afh[mt][2] = sAh[base + 4];
                afh[mt][3] = sAh[base + 8 * SPAD2 + 4];
                afl[mt][0] = sAl[base];
                afl[mt][1] = sAl[base + 8 * SPAD2];
                afl[mt][2] = sAl[base + 4];
                afl[mt][3] = sAl[base + 8 * SPAD2 + 4];
            }
#pragma unroll
            for (int nt = 0; nt < 4; nt++) {
                int base = (wc * 32 + nt * 8 + gq) * SPAD2 + kb;
                uint32_t bfh[2], bfl[2];
                bfh[0] = sBh[base];
                bfh[1] = sBh[base + 4];
                bfl[0] = sBl[base];
                bfl[1] = sBl[base + 4];
#pragma unroll
                for (int mt = 0; mt < 4; mt++) {
                    MMA_TF32(c[mt][nt], afh[mt], bfh);
                    MMA_TF32(c[mt][nt], afh[mt], bfl);
                    MMA_TF32(c[mt][nt], afl[mt], bfh);
                }
            }
        }
        __syncthreads();
        if (it + 1 < CH_PER_SPLIT) {
#pragma unroll
            for (int p = 0; p < 2; p++) {
                *(uint4*)&sAh[lrow[p] * SPAD2 + lc4[p] * 4] = rah[p];
                *(uint4*)&sAl[lrow[p] * SPAD2 + lc4[p] * 4] = ral[p];
                sBh[(bn0[p] + 0) * SPAD2 + bkk[p]] = rbh[p].x;
                sBh[(bn0[p] + 1) * SPAD2 + bkk[p]] = rbh[p].y;
                sBh[(bn0[p] + 2) * SPAD2 + bkk[p]] = rbh[p].z;
                sBh[(bn0[p] + 3) * SPAD2 + bkk[p]] = rbh[p].w;
                sBl[(bn0[p] + 0) * SPAD2 + bkk[p]] = rbl[p].x;
                sBl[(bn0[p] + 1) * SPAD2 + bkk[p]] = rbl[p].y;
                sBl[(bn0[p] + 2) * SPAD2 + bkk[p]] = rbl[p].z;
                sBl[(bn0[p] + 3) * SPAD2 + bkk[p]] = rbl[p].w;
            }
            __syncthreads();
        }
    }

    // epilogue: atomic accumulate partials
#pragma unroll
    for (int mt = 0; mt < 4; mt++) {
        int row0 = rowBase + wr * 64 + mt * 16 + gq;
#pragma unroll
        for (int nt = 0; nt < 4; nt++) {
            int col = wc * 32 + nt * 8 + tq * 2;
            atomicAdd(&Cm[(size_t)row0 * 128 + col],     c[mt][nt][0]);
            atomicAdd(&Cm[(size_t)row0 * 128 + col + 1], c[mt][nt][1]);
            atomicAdd(&Cm[(size_t)(row0 + 8) * 128 + col],     c[mt][nt][2]);
            atomicAdd(&Cm[(size_t)(row0 + 8) * 128 + col + 1], c[mt][nt][3]);
        }
    }
}

// ---------------- scalar fused attention (fp32, proven) --------------------
__global__ void __launch_bounds__(128)
attn_kernel(const int* __restrict__ positions) {
    __shared__ float4 kcs[DC][4];
    __shared__ float4 vcs[DC][4];
    const int h = blockIdx.y;
    const int tid = threadIdx.x;
    for (int p = tid; p < DC * 4; p += 128) {
        int c = p >> 2, d = p & 3;
        kcs[c][d] = *(const float4*)(g_kc + c * 128 + h * 16 + d * 4);
        vcs[c][d] = *(const float4*)(g_vc + c * 128 + h * 16 + d * 4);
    }
    __syncthreads();
    int n = blockIdx.x * 128 + tid;
    if (n >= NN) return;

    const int pos = positions[n];
    const float* qp = g_q + (size_t)n * 128 + h * 16;
    const float* pp = g_peq + (size_t)pos * 128 + h * 16;
    float4 q0 = *(const float4*)(qp + 0);
    float4 q1 = *(const float4*)(qp + 4);
    float4 q2 = *(const float4*)(qp + 8);
    float4 q3 = *(const float4*)(qp + 12);
    float4 p0 = *(const float4*)(pp + 0);
    float4 p1 = *(const float4*)(pp + 4);
    float4 p2 = *(const float4*)(pp + 8);
    float4 p3 = *(const float4*)(pp + 12);
    q0.x += p0.x; q0.y += p0.y; q0.z += p0.z; q0.w += p0.w;
    q1.x += p1.x; q1.y += p1.y; q1.z += p1.z; q1.w += p1.w;
    q2.x += p2.x; q2.y += p2.y; q2.z += p2.z; q2.w += p2.w;
    q3.x += p3.x; q3.y += p3.y; q3.z += p3.z; q3.w += p3.w;

    float s = 0.0f;
    float4 o0 = {0, 0, 0, 0}, o1 = {0, 0, 0, 0}, o2 = {0, 0, 0, 0}, o3 = {0, 0, 0, 0};

    for (int c = 0; c < DC; c++) {
        float4 k0 = kcs[c][0], k1 = kcs[c][1], k2 = kcs[c][2], k3 = kcs[c][3];
        float dot = q0.x * k0.x + q0.y * k0.y + q0.z * k0.z + q0.w * k0.w
                  + q1.x * k1.x + q1.y * k1.y + q1.z * k1.z + q1.w * k1.w
                  + q2.x * k2.x + q2.y * k2.y + q2.z * k2.z + q2.w * k2.w
                  + q3.x * k3.x + q3.y * k3.y + q3.z * k3.z + q3.w * k3.w;
        float p = __expf(dot * 0.25f);
        s += p;
        float4 v0 = vcs[c][0], v1 = vcs[c][1], v2 = vcs[c][2], v3 = vcs[c][3];
        o0.x += p * v0.x; o0.y += p * v0.y; o0.z += p * v0.z; o0.w += p * v0.w;
        o1.x += p * v1.x; o1.y += p * v1.y; o1.z += p * v1.z; o1.w += p * v1.w;
        o2.x += p * v2.x; o2.y += p * v2.y; o2.z += p * v2.z; o2.w += p * v2.w;
        o3.x += p * v3.x; o3.y += p * v3.y; o3.z += p * v3.z; o3.w += p * v3.w;
    }
    float inv = 1.0f / s;
    float* op = g_att + (size_t)n * 128 + h * 16;
    o0.x *= inv; o0.y *= inv; o0.z *= inv; o0.w *= inv;
    o1.x *= inv; o1.y *= inv; o1.z *= inv; o1.w *= inv;
    o2.x *= inv; o2.y *= inv; o2.z *= inv; o2.w *= inv;
    o3.x *= inv; o3.y *= inv; o3.z *= inv; o3.w *= inv;
    *(float4*)(op + 0) = o0;
    *(float4*)(op + 4) = o1;
    *(float4*)(op + 8) = o2;
    *(float4*)(op + 12) = o3;
}

// ---------------- small helpers ----------------
__global__ void zero_cc() {
    int i = blockIdx.x * blockDim.x + threadIdx.x;
    if (i < DC * 128) { g_kinc[i] = 0.0f; g_vinc[i] = 0.0f; }
}

__global__ void transpose_w(float* __restrict__ Wt, const float* __restrict__ W,
                            int N, int K) {
    int idx = blockIdx.x * blockDim.x + threadIdx.x;
    if (idx >= N * K) return;
    int n = idx / K;
    int k = idx - n * K;
    Wt[idx] = W[k * N + n];
}

__global__ void pack2t(float* __restrict__ Wt, const float* __restrict__ W1,
                       const float* __restrict__ W2, float* __restrict__ b,
                       const float* __restrict__ b1, const float* __restrict__ b2,
                       int hc, int K) {
    int idx = blockIdx.x * blockDim.x + threadIdx.x;
    int tot = 2 * hc * K;
    if (idx < tot) {
        int n = idx / K;
        int k = idx - n * K;
        Wt[idx] = (n < hc) ? W1[k * hc + n] : W2[k * hc + (n - hc)];
    }
    if (idx < 2 * hc) b[idx] = (idx < hc) ? b1[idx] : b2[idx - hc];
}

__global__ void pack_w12t(const float* __restrict__ gcn_W, const float* __restrict__ gcnA2_W,
                          const float* __restrict__ gcn_b, const float* __restrict__ gcnA2_b) {
    int idx = blockIdx.x * blockDim.x + threadIdx.x;
    if (idx < 512 * 512) {
        int n = idx >> 9;
        int k = idx & 511;
        g_W12t[idx] = (n < 256) ? gcn_W[k * 256 + n] : gcnA2_W[k * 256 + (n - 256)];
    }
    if (idx < 512) g_b12[idx] = (idx < 256) ? gcn_b[idx] : gcnA2_b[idx - 256];
}

// fold: Woabt[n][k] = sum_j Wo[k][j] * Wab[j][n]; bab2[n] = bab[n] + sum_j bo[j]*Wab[j][n]
__global__ void fold_woab(const float* __restrict__ Wo,
                          const float* __restrict__ tfa_W, const float* __restrict__ tga_W,
                          const float* __restrict__ bo,
                          const float* __restrict__ tfa_b, const float* __restrict__ tga_b) {
    int idx = blockIdx.x * blockDim.x + threadIdx.x;
    if (idx < 128 * 128) {
        int n = idx >> 7, k = idx & 127;
        float s = 0.f;
        for (int j = 0; j < 128; j++) {
            float wab = (n < 64) ? tfa_W[j * 64 + n] : tga_W[j * 64 + (n - 64)];
            s += Wo[k * 128 + j] * wab;
        }
        g_Woabt[n * 128 + k] = s;
    }
    if (idx < 128) {
        int n = idx;
        float s = (n < 64) ? tfa_b[n] : tga_b[n - 64];
        for (int j = 0; j < 128; j++) {
            float wab = (n < 64) ? tfa_W[j * 64 + n] : tga_W[j * 64 + (n - 64)];
            s += bo[j] * wab;
        }
        g_bab2[n] = s;
    }
}

// ---------------- CSR construction ----------------
__global__ void deg_zero() {
    int i = blockIdx.x * blockDim.x + threadIdx.x;
    if (i < NN) { g_deg[i] = 0; g_cnt[i] = 0; }
}
__global__ void deg_count(const int* __restrict__ adj) {
    int e = blockIdx.x * blockDim.x + threadIdx.x;
    if (e < EE) atomicAdd(&g_deg[adj[EE + e]], 1);
}
__global__ void __launch_bounds__(1024) scan_offsets() {
    __shared__ int partial[1024];
    const int tid = threadIdx.x;
    const int PER = (NN + 1023) / 1024;
    const int base = tid * PER;
    int s = 0;
#pragma unroll
    for (int i = 0; i < PER; i++) {
        int idx = base + i;
        if (idx < NN) s += g_deg[idx];
    }
    partial[tid] = s;
    __syncthreads();
    for (int off = 1; off < 1024; off <<= 1) {
        int v = 0;
        if (tid >= off) v = partial[tid - off];
        __syncthreads();
        if (tid >= off) partial[tid] += v;
        __syncthreads();
    }
    int run = (tid > 0) ? partial[tid - 1] : 0;
#pragma unroll
    for (int i = 0; i < PER; i++) {
        int idx = base + i;
        if (idx < NN) {
            g_off[idx] = run;
            int d = g_deg[idx];
            run += d;
            g_dinv[idx] = rsqrtf(1.0f + (float)d);
        }
    }
    if (tid == 0) g_off[NN] = EE;
}
__global__ void fill_csr(const int* __restrict__ adj) {
    int e = blockIdx.x * blockDim.x + threadIdx.x;
    if (e >= EE) return;
    int s = adj[e];
    int d = adj[EE + e];
    int pos = g_off[d] + atomicAdd(&g_cnt[d], 1);
    g_esrc[pos] = s;
}

// ---------------- row sums of Ek / Ev ----------------
__global__ void rowsums(const float* __restrict__ Ek, const float* __restrict__ Ev) {
    int gw = (blockIdx.x * blockDim.x + threadIdx.x) >> 5;
    int lane = threadIdx.x & 31;
    if (gw >= 2 * DC) return;
    const float* src = (gw < DC) ? Ek + (size_t)gw * NN : Ev + (size_t)(gw - DC) * NN;
    float s = 0.0f;
    for (int i = lane * 4; i < NN; i += 128) {
        float4 v = *(const float4*)(src + i);
        s += v.x + v.y + v.z + v.w;
    }
#pragma unroll
    for (int o = 16; o > 0; o >>= 1) s += __shfl_xor_sync(0xffffffffu, s, o);
    if (lane == 0) {
        if (gw < DC) g_rsk[gw] = s;
        else         g_rsv[gw - DC] = s;
    }
}

// ---------------- CSR gather + fused GCN finalize --------------------------
__global__ void __launch_bounds__(128) gcn_gather() {
    __shared__ int   s_src[128];
    __shared__ float s_coef[128];
    const int d = blockIdx.x;
    const int tid = threadIdx.x;
    const int beg = g_off[d];
    const int deg = g_off[d + 1] - beg;
    const float di = g_dinv[d];

    float4 acc = {0.f, 0.f, 0.f, 0.f};
    for (int c0 = 0; c0 < deg; c0 += 128) {
        int m = min(128, deg - c0);
        if (tid < m) {
            int s = g_esrc[beg + c0 + tid];
            s_src[tid] = s;
            s_coef[tid] = g_dinv[s] * di;
        }
        __syncthreads();
        int i = 0;
#pragma unroll 1
        for (; i + 4 <= m; i += 4) {
            const float4 h0 = *(const float4*)(g_h + (size_t)s_src[i + 0] * 512 + tid * 4);
            const float4 h1 = *(const float4*)(g_h + (size_t)s_src[i + 1] * 512 + tid * 4);
            const float4 h2 = *(const float4*)(g_h + (size_t)s_src[i + 2] * 512 + tid * 4);
            const float4 h3 = *(const float4*)(g_h + (size_t)s_src[i + 3] * 512 + tid * 4);
            float c0f = s_coef[i + 0], c1f = s_coef[i + 1];
            float c2f = s_coef[i + 2], c3f = s_coef[i + 3];
            acc.x += h0.x * c0f; acc.y += h0.y * c0f; acc.z += h0.z * c0f; acc.w += h0.w * c0f;
            acc.x += h1.x * c1f; acc.y += h1.y * c1f; acc.z += h1.z * c1f; acc.w += h1.w * c1f;
            acc.x += h2.x * c2f; acc.y += h2.y * c2f; acc.z += h2.z * c2f; acc.w += h2.w * c2f;
            acc.x += h3.x * c3f; acc.y += h3.y * c3f; acc.z += h3.z * c3f; acc.w += h3.w * c3f;
        }
        for (; i < m; i++) {
            const float4 hv = *(const float4*)(g_h + (size_t)s_src[i] * 512 + tid * 4);
            float cf = s_coef[i];
            acc.x += hv.x * cf; acc.y += hv.y * cf; acc.z += hv.z * cf; acc.w += hv.w * cf;
        }
        __syncthreads();
    }

    const int j = tid * 4;
    const float4 hd = *(const float4*)(g_h + (size_t)d * 512 + j);
    const float4 bb = *(const float4*)(g_b12 + j);
    const float d2 = di * di;
    float4 v;
    v.x = acc.x + hd.x * d2 + bb.x;
    v.y = acc.y + hd.y * d2 + bb.y;
    v.z = acc.z + hd.z * d2 + bb.z;
    v.w = acc.w + hd.w * d2 + bb.w;
    if (j < 256) {
        float4 o;
        o.x = 1.0f / (1.0f + __expf(-v.x));
        o.y = 1.0f / (1.0f + __expf(-v.y));
        o.z = 1.0f / (1.0f + __expf(-v.z));
        o.w = 1.0f / (1.0f + __expf(-v.w));
        *(float4*)(g_g1 + (size_t)d * 256 + j) = o;
    } else {
        *(float4*)(g_xa + (size_t)d * 256 + (j - 256)) = v;
    }
}

// ---------------- SGEMM (SIMT, small launches only) ------------------------
template <int ACT>
__global__ void __launch_bounds__(256)
sgemm2(const float* __restrict__ A, const float* __restrict__ B,
       const float* __restrict__ bias, const float* __restrict__ rowscale,
       float* __restrict__ C, int M, int N, int K) {
    __shared__ float As[2][16][128];
    __shared__ float Bs[2][16][128];
    const int tid = threadIdx.x;
    const int rowBase = blockIdx.y * 128;
    const int colBase = blockIdx.x * 128;

    const int lr = tid >> 1;
    const int lq = (tid & 1) * 8;
    const int br = tid >> 5;
    const int bc = (tid & 31) * 4;
    const int rm = tid >> 4;
    const int rn = tid & 15;

    const int arow = rowBase + lr;
    const bool aval = arow < M;
    const float* Aptr = A + (size_t)arow * K + lq;
    const float* Bptr = B + colBase + bc;

    float acc[8][8];
#pragma unroll
    for (int i = 0; i < 8; i++)
#pragma unroll
        for (int j = 0; j < 8; j++) acc[i][j] = 0.0f;

    const int niter = K >> 4;
    float4 a0, a1, b0, b1;
    a0 = aval ? *(const float4*)(Aptr + 0) : make_float4(0, 0, 0, 0);
    a1 = aval ? *(const float4*)(Aptr + 4) : make_float4(0, 0, 0, 0);
    b0 = *(const float4*)(Bptr + (size_t)br * N);
    b1 = *(const float4*)(Bptr + (size_t)(br + 8) * N);
    As[0][lq + 0][lr] = a0.x; As[0][lq + 1][lr] = a0.y;
    As[0][lq + 2][lr] = a0.z; As[0][lq + 3][lr] = a0.w;
    As[0][lq + 4][lr] = a1.x; As[0][lq + 5][lr] = a1.y;
    As[0][lq + 6][lr] = a1.z; As[0][lq + 7][lr] = a1.w;
    *(float4*)&Bs[0][br][bc] = b0;
    *(float4*)&Bs[0][br + 8][bc] = b1;
    __syncthreads();

    for (int it = 0; it < niter; it++) {
        const int cur = it & 1;
        if (it + 1 < niter) {
            const int k0 = (it + 1) << 4;
            a0 = aval ? *(const float4*)(Aptr + k0) : make_float4(0, 0, 0, 0);
            a1 = aval ? *(const float4*)(Aptr + k0 + 4) : make_float4(0, 0, 0, 0);
            b0 = *(const float4*)(Bptr + (size_t)(k0 + br) * N);
            b1 = *(const float4*)(Bptr + (size_t)(k0 + br + 8) * N);
        }
#pragma unroll
        for (int k = 0; k < 16; k++) {
            float4 av0 = *(const float4*)&As[cur][k][rm * 8];
            float4 av1 = *(const float4*)&As[cur][k][rm * 8 + 4];
            float4 bv0 = *(const float4*)&Bs[cur][k][rn * 8];
            float4 bv1 = *(const float4*)&Bs[cur][k][rn * 8 + 4];
            float av[8] = {av0.x, av0.y, av0.z, av0.w, av1.x, av1.y, av1.z, av1.w};
            float bv[8] = {bv0.x, bv0.y, bv0.z, bv0.w, bv1.x, bv1.y, bv1.z, bv1.w};
#pragma unroll
            for (int i = 0; i < 8; i++)
#pragma unroll
                for (int j = 0; j < 8; j++) acc[i][j] += av[i] * bv[j];
        }
        if (it + 1 < niter) {
            const int nxt = cur ^ 1;
            As[nxt][lq + 0][lr] = a0.x; As[nxt][lq + 1][lr] = a0.y;
            As[nxt][lq + 2][lr] = a0.z; As[nxt][lq + 3][lr] = a0.w;
            As[nxt][lq + 4][lr] = a1.x; As[nxt][lq + 5][lr] = a1.y;
            As[nxt][lq + 6][lr] = a1.z; As[nxt][lq + 7][lr] = a1.w;
            *(float4*)&Bs[nxt][br][bc] = b0;
            *(float4*)&Bs[nxt][br + 8][bc] = b1;
        }
        __syncthreads();
    }

#pragma unroll
    for (int i = 0; i < 8; i++) {
        int row = rowBase + rm * 8 + i;
        if (row >= M) continue;
        float rsc = (ACT == 2) ? rowscale[row] : 1.0f;
        int col0 = colBase + rn * 8;
#pragma unroll
        for (int j4 = 0; j4 < 2; j4++) {
            float4 o;
            float* op = &o.x;
#pragma unroll
            for (int j = 0; j < 4; j++) {
                int jj = j4 * 4 + j;
                float v = acc[i][jj];
                if (bias) v += rsc * bias[col0 + jj];
                if (ACT == 1) v = (v >= 0.0f) ? v : 0.01f * v;
                op[j] = v;
            }
            *(float4*)&C[(size_t)row * N + col0 + j4 * 4] = o;
        }
    }
}

// ---------------- row norms of tfa / tga ----------------
__global__ void norms_kernel() {
    int n = blockIdx.x * blockDim.x + threadIdx.x;
    if (n >= NN) return;
    const float4* a = (const float4*)(g_ab + (size_t)n * 128);
    float sa = 0.0f, sb = 0.0f;
#pragma unroll
    for (int i = 0; i < 16; i++) {
        float4 v = a[i];
        sa += v.x * v.x + v.y * v.y + v.z * v.z + v.w * v.w;
    }
#pragma unroll
    for (int i = 16; i < 32; i++) {
        float4 v = a[i];
        sb += v.x * v.x + v.y * v.y + v.z * v.z + v.w * v.w;
    }
    g_na[n] = sqrtf(sa);
    g_nb[n] = sqrtf(sb);
}

// ---------------- final cosine for 200K pairs ----------------
__global__ void final_pairs(const int* __restrict__ ts, float* __restrict__ out) {
    int t = blockIdx.x * blockDim.x + threadIdx.x;
    if (t >= NT) return;
    int i = ts[2 * t];
    int j = ts[2 * t + 1];
    const float4* a = (const float4*)(g_ab + (size_t)i * 128);
    const float4* b = (const float4*)(g_ab + (size_t)j * 128 + 64);
    float dot = 0.0f;
#pragma unroll
    for (int p = 0; p < 16; p++) {
        float4 av = a[p];
        float4 bv = b[p];
        dot += av.x * bv.x + av.y * bv.y + av.z * bv.z + av.w * bv.w;
    }
    out[t] = dot / fmaxf(g_na[i] * g_nb[j], 1e-8f);
}

// ---------------- host launcher ----------------
static float* symaddr(const void* sym) {
    void* p = nullptr;
    cudaGetSymbolAddress(&p, sym);
    return (float*)p;
}

extern "C" void kernel_launch(void* const* d_in, const int* in_sizes, int n_in,
                              void* d_out, int out_size) {
    const int*   train_sample = (const int*)d_in[1];
    const float* data_feature = (const float*)d_in[2];
    const int*   adj          = (const int*)d_in[3];
    const int*   positions    = (const int*)d_in[4];
    const float* gcn_W   = (const float*)d_in[5];
    const float* gcn_b   = (const float*)d_in[6];
    const float* gcnA2_W = (const float*)d_in[7];
    const float* gcnA2_b = (const float*)d_in[8];
    const float* lin_W   = (const float*)d_in[9];
    const float* lin_b   = (const float*)d_in[10];
    const float* tf_W    = (const float*)d_in[11];
    const float* tf_b    = (const float*)d_in[12];
    const float* tg_W    = (const float*)d_in[13];
    const float* tg_b    = (const float*)d_in[14];
    const float* Wq = (const float*)d_in[15];
    const float* bq = (const float*)d_in[16];
    const float* Wk = (const float*)d_in[17];
    const float* bk = (const float*)d_in[18];
    const float* Wv = (const float*)d_in[19];
    const float* bv = (const float*)d_in[20];
    const float* Wo = (const float*)d_in[21];
    const float* bo = (const float*)d_in[22];
    const float* Ek = (const float*)d_in[23];
    const float* Ev = (const float*)d_in[24];
    const float* pos_emb = (const float*)d_in[25];
    const float* tfa_W = (const float*)d_in[26];
    const float* tfa_b = (const float*)d_in[27];
    const float* tga_W = (const float*)d_in[28];
    const float* tga_b = (const float*)d_in[29];

    float* d_lint  = symaddr(g_lint);
    float* d_tftgt = symaddr(g_tftgt);
    float* d_btftg = symaddr(g_btftg);
    float* d_Wqt   = symaddr(g_Wqt);
    float* d_Woabt = symaddr(g_Woabt);
    float* d_bab2  = symaddr(g_bab2);
    float* d_W12t  = symaddr(g_W12t);
    float* d_g1   = symaddr(g_g1);
    float* d_xa   = symaddr(g_xa);
    float* d_xg   = symaddr(g_xg);
    float* d_tftg = symaddr(g_tftg);
    float* d_q    = symaddr(g_q);
    float* d_peq  = symaddr(g_peq);
    float* d_kinc = symaddr(g_kinc);
    float* d_vinc = symaddr(g_vinc);
    float* d_rsk  = symaddr(g_rsk);
    float* d_rsv  = symaddr(g_rsv);
    float* d_kc   = symaddr(g_kc);
    float* d_vc   = symaddr(g_vc);
    float* d_att  = symaddr(g_att);
    float* d_ab   = symaddr(g_ab);
    float* d_h    = symaddr(g_h);

    // 1. weight packs (all transposed for mma B operand) + Wo@Wab fold
    pack_w12t<<<(512 * 512 + 255) / 256, 256>>>(gcn_W, gcnA2_W, gcn_b, gcnA2_b);
    transpose_w<<<(128 * 256 + 255) / 256, 256>>>(d_lint, lin_W, 128, 256);
    pack2t<<<(256 * 256 + 255) / 256, 256>>>(d_tftgt, tf_W, tg_W, d_btftg, tf_b, tg_b, 128, 256);
    transpose_w<<<(128 * 128 + 255) / 256, 256>>>(d_Wqt, Wq, 128, 128);
    fold_woab<<<(128 * 128 + 255) / 256, 256>>>(Wo, tfa_W, tga_W, bo, tfa_b, tga_b);

    // 2. CSR construction + Ek/Ev row sums
    deg_zero<<<(NN + 255) / 256, 256>>>();
    deg_count<<<(EE + 255) / 256, 256>>>(adj);
    scan_offsets<<<1, 1024>>>();
    fill_csr<<<(EE + 255) / 256, 256>>>(adj);
    rowsums<<<(2 * DC * 32 + 255) / 256, 256>>>(Ek, Ev);

    // 3. h = data_feature @ [gcn_W | gcnA2_W]  — tf32 mma
    mma_gemm<0, 0><<<dim3(4, 157), 256>>>(data_feature, d_W12t, nullptr, d_h,
                                          NN, 512, 512, nullptr, nullptr);

    // 4. CSR gather + fused finalize -> g1 (sigmoid), xa
    gcn_gather<<<NN, 128>>>();

    // 5. x_g; [tf|tg] with fused kin = tf + pos_emb[pos]
    mma_gemm<1, 0><<<dim3(1, 157), 256>>>(d_g1, d_lint, lin_b, d_xg,
                                          NN, 128, 256, nullptr, nullptr);
    mma_gemm<1, 1><<<dim3(2, 157), 256>>>(d_xa, d_tftgt, d_btftg, d_tftg,
                                          NN, 256, 256, positions, pos_emb);

    // 6. q = xg@Wq + bq (mma); peq = pos_emb@Wq (SIMT, tiny)
    mma_gemm<0, 0><<<dim3(1, 157), 256>>>(d_xg, d_Wqt, bq, d_q,
                                          NN, 128, 128, nullptr, nullptr);
    sgemm2<0><<<dim3(1, 4), 256>>>(pos_emb, Wq, nullptr, nullptr, d_peq, 512, 128, 128);

    // 7. kinc = Ek@kin, vinc = Ev@tg (3xTF32 split-K mma), then project at DC
    zero_cc<<<(DC * 128 + 255) / 256, 256>>>();
    splitk_mma<<<dim3(1, 2, 2 * NSPLIT), 256>>>(Ek, Ev);
    sgemm2<2><<<dim3(1, 2), 256>>>(d_kinc, Wk, bk, d_rsk, d_kc, DC, 128, 128);
    sgemm2<2><<<dim3(1, 2), 256>>>(d_vinc, Wv, bv, d_rsv, d_vc, DC, 128, 128);

    // 8. scalar fp32 attention (proven fast + accurate)
    attn_kernel<<<dim3(157, 8), 128>>>(positions);

    // 9. ab = leaky(att @ (Wo@Wab) + bab2)  — folded, single tf32 mma
    mma_gemm<1, 0><<<dim3(1, 157), 256>>>(d_att, d_Woabt, d_bab2, d_ab,
                                          NN, 128, 128, nullptr, nullptr);

    // 10. norms + final cosine pairs
    norms_kernel<<<(NN + 255) / 256, 256>>>();
    final_pairs<<<(NT + 255) / 256, 256>>>(train_sample, (float*)d_out);
}

// round 16
// speedup vs baseline: 1.0717x; 1.0717x over previous
#include <cuda_runtime.h>
#include <math.h>
#include <stdint.h>

// ---------------- problem constants ----------------
constexpr int NN   = 20000;
constexpr int EE   = 320000;
constexpr int NT   = 200000;
constexpr int DC   = 256;

// ---------------- scratch (static device globals; no runtime alloc) --------
__device__ float g_W12t[512 * 512];        // transposed fused weights [n][k]
__device__ float g_b12[512];
__device__ float g_lint[128 * 256];        // lin_W^T
__device__ float g_tftgt[256 * 256];       // [tf_W | tg_W]^T
__device__ float g_btftg[256];
__device__ float g_Wqt[128 * 128];
__device__ float g_Woabt[128 * 128];       // (Wo @ [tfa_W|tga_W])^T
__device__ float g_bab2[128];              // bo@Wab + [tfa_b|tga_b]

__device__ float g_h[(size_t)NN * 512];    // [h_gcn1 | h_gcn2]
__device__ float g_dinv[NN];

__device__ int g_deg[NN];
__device__ int g_cnt[NN];
__device__ int g_off[NN + 1];
__device__ int g_esrc[EE];

__device__ float g_g1[(size_t)NN * 256];
__device__ float g_xa[(size_t)NN * 256];
__device__ float g_xg[(size_t)NN * 128];
__device__ float g_tftg[(size_t)NN * 256];

__device__ float g_kin[(size_t)NN * 128];
__device__ float g_q[(size_t)NN * 128];
__device__ float g_peq[512 * 128];

__device__ float g_kinc[DC * 128];
__device__ float g_vinc[DC * 128];
__device__ float g_rsk[DC];
__device__ float g_rsv[DC];
__device__ float g_kc[DC * 128];
__device__ float g_vc[DC * 128];

__device__ float g_att[(size_t)NN * 128];
__device__ float g_ab[(size_t)NN * 128];
__device__ float g_na[NN];
__device__ float g_nb[NN];

// ---------------- tf32 helpers ----------------
__device__ __forceinline__ uint32_t cvt_tf32(float f) {
    uint32_t u;
    asm("cvt.rna.tf32.f32 %0, %1;" : "=r"(u) : "f"(f));
    return u;
}
__device__ __forceinline__ uint4 cvt_tf32x4(float4 v) {
    uint4 r;
    r.x = cvt_tf32(v.x); r.y = cvt_tf32(v.y);
    r.z = cvt_tf32(v.z); r.w = cvt_tf32(v.w);
    return r;
}
#define MMA_TF32(c, a, b) \
    asm volatile( \
        "mma.sync.aligned.m16n8k8.row.col.f32.tf32.tf32.f32 " \
        "{%0,%1,%2,%3}, {%4,%5,%6,%7}, {%8,%9}, {%0,%1,%2,%3};" \
        : "+f"((c)[0]), "+f"((c)[1]), "+f"((c)[2]), "+f"((c)[3]) \
        : "r"((a)[0]), "r"((a)[1]), "r"((a)[2]), "r"((a)[3]), \
          "r"((b)[0]), "r"((b)[1]))

// ---------------- generic tf32 mma.sync GEMM: C = act(A@Bt^T + bias) -------
// BM=128, BN=128, BK=32. 256 threads = 8 warps; warp tile 64x32 (4x4 m16n8k8).
// ACT: 0 = none, 1 = leaky relu. KIN: also write g_kin for cols<128.
constexpr int SPAD = 36;
template <int ACT, int KIN>
__global__ void __launch_bounds__(256)
mma_gemm(const float* __restrict__ A, const float* __restrict__ Bt,
         const float* __restrict__ bias, float* __restrict__ C,
         int M, int N, int K,
         const int* __restrict__ positions, const float* __restrict__ pos_emb) {
    __shared__ uint32_t sA[128 * SPAD];
    __shared__ uint32_t sB[128 * SPAD];
    const int tid = threadIdx.x;
    const int lane = tid & 31, wid = tid >> 5;
    const int wr = wid >> 2, wc = wid & 3;
    const int gq = lane >> 2, tq = lane & 3;
    const int rowBase = blockIdx.y * 128;
    const int colBase = blockIdx.x * 128;

    float c[4][4][4];
#pragma unroll
    for (int mt = 0; mt < 4; mt++)
#pragma unroll
        for (int nt = 0; nt < 4; nt++)
#pragma unroll
            for (int r = 0; r < 4; r++) c[mt][nt][r] = 0.0f;

    int lrow[4], lc4[4];
#pragma unroll
    for (int p = 0; p < 4; p++) {
        int idx = tid + p * 256;
        lrow[p] = idx >> 3;
        lc4[p] = idx & 7;
    }

    uint4 ra[4], rb[4];
#pragma unroll
    for (int p = 0; p < 4; p++) {
        int arow = rowBase + lrow[p];
        float4 av = (arow < M)
            ? *(const float4*)(A + (size_t)arow * K + lc4[p] * 4)
            : make_float4(0.f, 0.f, 0.f, 0.f);
        ra[p] = cvt_tf32x4(av);
        float4 bv = *(const float4*)(Bt + (size_t)(colBase + lrow[p]) * K + lc4[p] * 4);
        rb[p] = cvt_tf32x4(bv);
    }
#pragma unroll
    for (int p = 0; p < 4; p++) {
        *(uint4*)&sA[lrow[p] * SPAD + lc4[p] * 4] = ra[p];
        *(uint4*)&sB[lrow[p] * SPAD + lc4[p] * 4] = rb[p];
    }
    __syncthreads();

    const int niter = K >> 5;
    for (int it = 0; it < niter; it++) {
        if (it + 1 < niter) {
            const int k0 = (it + 1) * 32;
#pragma unroll
            for (int p = 0; p < 4; p++) {
                int arow = rowBase + lrow[p];
                float4 av = (arow < M)
                    ? *(const float4*)(A + (size_t)arow * K + k0 + lc4[p] * 4)
                    : make_float4(0.f, 0.f, 0.f, 0.f);
                ra[p] = cvt_tf32x4(av);
                float4 bv = *(const float4*)(Bt + (size_t)(colBase + lrow[p]) * K + k0 + lc4[p] * 4);
                rb[p] = cvt_tf32x4(bv);
            }
        }
#pragma unroll
        for (int ks = 0; ks < 4; ks++) {
            const int kb = ks * 8 + tq;
            uint32_t af[4][4];
#pragma unroll
            for (int mt = 0; mt < 4; mt++) {
                int base = (wr * 64 + mt * 16 + gq) * SPAD + kb;
                af[mt][0] = sA[base];
                af[mt][1] = sA[base + 8 * SPAD];
                af[mt][2] = sA[base + 4];
                af[mt][3] = sA[base + 8 * SPAD + 4];
            }
            uint32_t bf[4][2];
#pragma unroll
            for (int nt = 0; nt < 4; nt++) {
                int base = (wc * 32 + nt * 8 + gq) * SPAD + kb;
                bf[nt][0] = sB[base];
                bf[nt][1] = sB[base + 4];
            }
#pragma unroll
            for (int mt = 0; mt < 4; mt++)
#pragma unroll
                for (int nt = 0; nt < 4; nt++)
                    MMA_TF32(c[mt][nt], af[mt], bf[nt]);
        }
        __syncthreads();
        if (it + 1 < niter) {
#pragma unroll
            for (int p = 0; p < 4; p++) {
                *(uint4*)&sA[lrow[p] * SPAD + lc4[p] * 4] = ra[p];
                *(uint4*)&sB[lrow[p] * SPAD + lc4[p] * 4] = rb[p];
            }
            __syncthreads();
        }
    }

#pragma unroll
    for (int mt = 0; mt < 4; mt++) {
        int row0 = rowBase + wr * 64 + mt * 16 + gq;
#pragma unroll
        for (int nt = 0; nt < 4; nt++) {
            int col = colBase + wc * 32 + nt * 8 + tq * 2;
            float b0 = 0.f, b1 = 0.f;
            if (bias) {
                float2 bb = *(const float2*)(bias + col);
                b0 = bb.x; b1 = bb.y;
            }
            float v0 = c[mt][nt][0] + b0, v1 = c[mt][nt][1] + b1;
            float v2 = c[mt][nt][2] + b0, v3 = c[mt][nt][3] + b1;
            if (ACT == 1) {
                v0 = (v0 >= 0.f) ? v0 : 0.01f * v0;
                v1 = (v1 >= 0.f) ? v1 : 0.01f * v1;
                v2 = (v2 >= 0.f) ? v2 : 0.01f * v2;
                v3 = (v3 >= 0.f) ? v3 : 0.01f * v3;
            }
            if (row0 < M) {
                float2 o = { v0, v1 };
                *(float2*)(C + (size_t)row0 * N + col) = o;
                if (KIN && col < 128) {
                    float2 pe = *(const float2*)(pos_emb + (size_t)positions[row0] * 128 + col);
                    float2 kk = { v0 + pe.x, v1 + pe.y };
                    *(float2*)(g_kin + (size_t)row0 * 128 + col) = kk;
                }
            }
            if (row0 + 8 < M) {
                float2 o = { v2, v3 };
                *(float2*)(C + (size_t)(row0 + 8) * N + col) = o;
                if (KIN && col < 128) {
                    float2 pe = *(const float2*)(pos_emb + (size_t)positions[row0 + 8] * 128 + col);
                    float2 kk = { v2 + pe.x, v3 + pe.y };
                    *(float2*)(g_kin + (size_t)(row0 + 8) * 128 + col) = kk;
                }
            }
        }
    }
}

// ---------------- split-K SIMT fp32 GEMM: kinc = Ek@kin, vinc = Ev@tg ------
// exact fp32; L2/latency-bound so SIMT matches tf32-mma speed here.
// M=256(DC), N=128, K=20000. BM=BN=64, BK=32, 25 k-iters per split, 25 splits.
__global__ void __launch_bounds__(256)
splitk_ckv(const float* __restrict__ Ekm, const float* __restrict__ Evm) {
    const int mat = blockIdx.z & 1;
    const int split = blockIdx.z >> 1;
    const float* Am = mat ? Evm : Ekm;
    const float* Xm = mat ? (g_tftg + 128) : g_kin;
    const int ldb = mat ? 256 : 128;
    float* Cm = mat ? g_vinc : g_kinc;

    const int rowBase = blockIdx.y * 64;
    const int colBase = blockIdx.x * 64;
    const int tid = threadIdx.x;
    const int rm = tid >> 4, rn = tid & 15;

    __shared__ float As[32][64];
    __shared__ float Bs[32][64];

    float acc[4][4];
#pragma unroll
    for (int i = 0; i < 4; i++)
#pragma unroll
        for (int j = 0; j < 4; j++) acc[i][j] = 0.0f;

    const int kstart = split * 25 * 32;
    for (int it = 0; it < 25; it++) {
        int kbase = kstart + it * 32;
        __syncthreads();
#pragma unroll
        for (int pp = 0; pp < 2; pp++) {
            int p = tid + pp * 256;
            int row = p >> 3;
            int kq = (p & 7) * 4;
            float4 a4 = *(const float4*)(Am + (size_t)(rowBase + row) * NN + kbase + kq);
            As[kq + 0][row] = a4.x;
            As[kq + 1][row] = a4.y;
            As[kq + 2][row] = a4.z;
            As[kq + 3][row] = a4.w;
            int krow = p >> 4;
            int cq = (p & 15) * 4;
            float4 b4 = *(const float4*)(Xm + (size_t)(kbase + krow) * ldb + colBase + cq);
            *(float4*)&Bs[krow][cq] = b4;
        }
        __syncthreads();
#pragma unroll
        for (int k = 0; k < 32; k++) {
            float4 a4 = *(float4*)&As[k][rm * 4];
            float4 b4 = *(float4*)&Bs[k][rn * 4];
            float av[4] = {a4.x, a4.y, a4.z, a4.w};
            float bv[4] = {b4.x, b4.y, b4.z, b4.w};
#pragma unroll
            for (int i = 0; i < 4; i++)
#pragma unroll
                for (int j = 0; j < 4; j++) acc[i][j] += av[i] * bv[j];
        }
    }
#pragma unroll
    for (int i = 0; i < 4; i++)
#pragma unroll
        for (int j = 0; j < 4; j++)
            atomicAdd(&Cm[(size_t)(rowBase + rm * 4 + i) * 128 + colBase + rn * 4 + j],
                      acc[i][j]);
}

// ---------------- fused kc/vc projection (one launch, z selects matrix) ----
// C = A @ B + rowscale[row]*bias[col];  M=256, N=128, K=128. BK=16 dbuf.
__global__ void __launch_bounds__(256)
proj_ckv(const float* __restrict__ Wk, const float* __restrict__ bk,
         const float* __restrict__ Wv, const float* __restrict__ bv) {
    const int mat = blockIdx.z;
    const float* A = mat ? g_vinc : g_kinc;
    const float* B = mat ? Wv : Wk;
    const float* bias = mat ? bv : bk;
    const float* rowscale = mat ? g_rsv : g_rsk;
    float* C = mat ? g_vc : g_kc;
    const int M = 256, N = 128, K = 128;

    __shared__ float As[2][16][128];
    __shared__ float Bs[2][16][128];
    const int tid = threadIdx.x;
    const int rowBase = blockIdx.y * 128;

    const int lr = tid >> 1;
    const int lq = (tid & 1) * 8;
    const int br = tid >> 5;
    const int bc = (tid & 31) * 4;
    const int rm = tid >> 4;
    const int rn = tid & 15;

    const float* Aptr = A + (size_t)(rowBase + lr) * K + lq;
    const float* Bptr = B + bc;

    float acc[8][8];
#pragma unroll
    for (int i = 0; i < 8; i++)
#pragma unroll
        for (int j = 0; j < 8; j++) acc[i][j] = 0.0f;

    const int niter = K >> 4;
    float4 a0, a1, b0, b1;
    a0 = *(const float4*)(Aptr + 0);
    a1 = *(const float4*)(Aptr + 4);
    b0 = *(const float4*)(Bptr + (size_t)br * N);
    b1 = *(const float4*)(Bptr + (size_t)(br + 8) * N);
    As[0][lq + 0][lr] = a0.x; As[0][lq + 1][lr] = a0.y;
    As[0][lq + 2][lr] = a0.z; As[0][lq + 3][lr] = a0.w;
    As[0][lq + 4][lr] = a1.x; As[0][lq + 5][lr] = a1.y;
    As[0][lq + 6][lr] = a1.z; As[0][lq + 7][lr] = a1.w;
    *(float4*)&Bs[0][br][bc] = b0;
    *(float4*)&Bs[0][br + 8][bc] = b1;
    __syncthreads();

    for (int it = 0; it < niter; it++) {
        const int cur = it & 1;
        if (it + 1 < niter) {
            const int k0 = (it + 1) << 4;
            a0 = *(const float4*)(Aptr + k0);
            a1 = *(const float4*)(Aptr + k0 + 4);
            b0 = *(const float4*)(Bptr + (size_t)(k0 + br) * N);
            b1 = *(const float4*)(Bptr + (size_t)(k0 + br + 8) * N);
        }
#pragma unroll
        for (int k = 0; k < 16; k++) {
            float4 av0 = *(const float4*)&As[cur][k][rm * 8];
            float4 av1 = *(const float4*)&As[cur][k][rm * 8 + 4];
            float4 bv0 = *(const float4*)&Bs[cur][k][rn * 8];
            float4 bv1 = *(const float4*)&Bs[cur][k][rn * 8 + 4];
            float av[8] = {av0.x, av0.y, av0.z, av0.w, av1.x, av1.y, av1.z, av1.w};
            float bvv[8] = {bv0.x, bv0.y, bv0.z, bv0.w, bv1.x, bv1.y, bv1.z, bv1.w};
#pragma unroll
            for (int i = 0; i < 8; i++)
#pragma unroll
                for (int j = 0; j < 8; j++) acc[i][j] += av[i] * bvv[j];
        }
        if (it + 1 < niter) {
            const int nxt = cur ^ 1;
            As[nxt][lq + 0][lr] = a0.x; As[nxt][lq + 1][lr] = a0.y;
            As[nxt][lq + 2][lr] = a0.z; As[nxt][lq + 3][lr] = a0.w;
            As[nxt][lq + 4][lr] = a1.x; As[nxt][lq + 5][lr] = a1.y;
            As[nxt][lq + 6][lr] = a1.z; As[nxt][lq + 7][lr] = a1.w;
            *(float4*)&Bs[nxt][br][bc] = b0;
            *(float4*)&Bs[nxt][br + 8][bc] = b1;
        }
        __syncthreads();
    }

#pragma unroll
    for (int i = 0; i < 8; i++) {
        int row = rowBase + rm * 8 + i;
        float rsc = rowscale[row];
        int col0 = rn * 8;
#pragma unroll
        for (int j4 = 0; j4 < 2; j4++) {
            float4 o;
            float* op = &o.x;
#pragma unroll
            for (int j = 0; j < 4; j++) {
                int jj = j4 * 4 + j;
                op[j] = acc[i][jj] + rsc * bias[col0 + jj];
            }
            *(float4*)&C[(size_t)row * N + col0 + j4 * 4] = o;
        }
    }
}

// ---------------- scalar fused attention (fp32, proven) --------------------
__global__ void __launch_bounds__(128)
attn_kernel(const int* __restrict__ positions) {
    __shared__ float4 kcs[DC][4];
    __shared__ float4 vcs[DC][4];
    const int h = blockIdx.y;
    const int tid = threadIdx.x;
    for (int p = tid; p < DC * 4; p += 128) {
        int c = p >> 2, d = p & 3;
        kcs[c][d] = *(const float4*)(g_kc + c * 128 + h * 16 + d * 4);
        vcs[c][d] = *(const float4*)(g_vc + c * 128 + h * 16 + d * 4);
    }
    __syncthreads();
    int n = blockIdx.x * 128 + tid;
    if (n >= NN) return;

    const int pos = positions[n];
    const float* qp = g_q + (size_t)n * 128 + h * 16;
    const float* pp = g_peq + (size_t)pos * 128 + h * 16;
    float4 q0 = *(const float4*)(qp + 0);
    float4 q1 = *(const float4*)(qp + 4);
    float4 q2 = *(const float4*)(qp + 8);
    float4 q3 = *(const float4*)(qp + 12);
    float4 p0 = *(const float4*)(pp + 0);
    float4 p1 = *(const float4*)(pp + 4);
    float4 p2 = *(const float4*)(pp + 8);
    float4 p3 = *(const float4*)(pp + 12);
    q0.x += p0.x; q0.y += p0.y; q0.z += p0.z; q0.w += p0.w;
    q1.x += p1.x; q1.y += p1.y; q1.z += p1.z; q1.w += p1.w;
    q2.x += p2.x; q2.y += p2.y; q2.z += p2.z; q2.w += p2.w;
    q3.x += p3.x; q3.y += p3.y; q3.z += p3.z; q3.w += p3.w;

    float s = 0.0f;
    float4 o0 = {0, 0, 0, 0}, o1 = {0, 0, 0, 0}, o2 = {0, 0, 0, 0}, o3 = {0, 0, 0, 0};

    for (int c = 0; c < DC; c++) {
        float4 k0 = kcs[c][0], k1 = kcs[c][1], k2 = kcs[c][2], k3 = kcs[c][3];
        float dot = q0.x * k0.x + q0.y * k0.y + q0.z * k0.z + q0.w * k0.w
                  + q1.x * k1.x + q1.y * k1.y + q1.z * k1.z + q1.w * k1.w
                  + q2.x * k2.x + q2.y * k2.y + q2.z * k2.z + q2.w * k2.w
                  + q3.x * k3.x + q3.y * k3.y + q3.z * k3.z + q3.w * k3.w;
        float p = __expf(dot * 0.25f);
        s += p;
        float4 v0 = vcs[c][0], v1 = vcs[c][1], v2 = vcs[c][2], v3 = vcs[c][3];
        o0.x += p * v0.x; o0.y += p * v0.y; o0.z += p * v0.z; o0.w += p * v0.w;
        o1.x += p * v1.x; o1.y += p * v1.y; o1.z += p * v1.z; o1.w += p * v1.w;
        o2.x += p * v2.x; o2.y += p * v2.y; o2.z += p * v2.z; o2.w += p * v2.w;
        o3.x += p * v3.x; o3.y += p * v3.y; o3.z += p * v3.z; o3.w += p * v3.w;
    }
    float inv = 1.0f / s;
    float* op = g_att + (size_t)n * 128 + h * 16;
    o0.x *= inv; o0.y *= inv; o0.z *= inv; o0.w *= inv;
    o1.x *= inv; o1.y *= inv; o1.z *= inv; o1.w *= inv;
    o2.x *= inv; o2.y *= inv; o2.z *= inv; o2.w *= inv;
    o3.x *= inv; o3.y *= inv; o3.z *= inv; o3.w *= inv;
    *(float4*)(op + 0) = o0;
    *(float4*)(op + 4) = o1;
    *(float4*)(op + 8) = o2;
    *(float4*)(op + 12) = o3;
}

// ---------------- merged weight packs (one launch) --------------------------
// segments: [0, 262144) W12t+b12 | lint 32768 | tftgt 65536 (+btftg) | Wqt 16384
__global__ void pack_all(const float* __restrict__ gcn_W, const float* __restrict__ gcnA2_W,
                         const float* __restrict__ gcn_b, const float* __restrict__ gcnA2_b,
                         const float* __restrict__ lin_W,
                         const float* __restrict__ tf_W, const float* __restrict__ tg_W,
                         const float* __restrict__ tf_b, const float* __restrict__ tg_b,
                         const float* __restrict__ Wq) {
    int idx = blockIdx.x * blockDim.x + threadIdx.x;
    if (idx < 512 * 512) {
        int n = idx >> 9, k = idx & 511;
        g_W12t[idx] = (n < 256) ? gcn_W[k * 256 + n] : gcnA2_W[k * 256 + (n - 256)];
        if (idx < 512) g_b12[idx] = (idx < 256) ? gcn_b[idx] : gcnA2_b[idx - 256];
        return;
    }
    int r = idx - 512 * 512;
    if (r < 128 * 256) {                    // lint[n][k], n<128, K=256
        int n = r >> 8, k = r & 255;
        g_lint[r] = lin_W[k * 128 + n];
        return;
    }
    r -= 128 * 256;
    if (r < 256 * 256) {                    // tftgt[n][k], n<256, K=256
        int n = r >> 8, k = r & 255;
        g_tftgt[r] = (n < 128) ? tf_W[k * 128 + n] : tg_W[k * 128 + (n - 128)];
        if (r < 256) g_btftg[r] = (r < 128) ? tf_b[r] : tg_b[r - 128];
        return;
    }
    r -= 256 * 256;
    if (r < 128 * 128) {                    // Wqt[n][k]
        int n = r >> 7, k = r & 127;
        g_Wqt[r] = Wq[k * 128 + n];
    }
}
constexpr int PACK_TOTAL = 512 * 512 + 128 * 256 + 256 * 256 + 128 * 128;

// fold: Woabt[n][k] = sum_j Wo[k][j] * Wab[j][n]; bab2[n] = bab[n] + sum_j bo[j]*Wab[j][n]
__global__ void fold_woab(const float* __restrict__ Wo,
                          const float* __restrict__ tfa_W, const float* __restrict__ tga_W,
                          const float* __restrict__ bo,
                          const float* __restrict__ tfa_b, const float* __restrict__ tga_b) {
    int idx = blockIdx.x * blockDim.x + threadIdx.x;
    if (idx < 128 * 128) {
        int n = idx >> 7, k = idx & 127;
        float s = 0.f;
        for (int j = 0; j < 128; j++) {
            float wab = (n < 64) ? tfa_W[j * 64 + n] : tga_W[j * 64 + (n - 64)];
            s += Wo[k * 128 + j] * wab;
        }
        g_Woabt[n * 128 + k] = s;
    }
    if (idx < 128) {
        int n = idx;
        float s = (n < 64) ? tfa_b[n] : tga_b[n - 64];
        for (int j = 0; j < 128; j++) {
            float wab = (n < 64) ? tfa_W[j * 64 + n] : tga_W[j * 64 + (n - 64)];
            s += bo[j] * wab;
        }
        g_bab2[n] = s;
    }
}

// ---------------- CSR construction (deg_zero also zeroes kinc/vinc) --------
__global__ void deg_zero() {
    int i = blockIdx.x * blockDim.x + threadIdx.x;
    if (i < NN) { g_deg[i] = 0; g_cnt[i] = 0; }
    if (i < DC * 128) { g_kinc[i] = 0.0f; g_vinc[i] = 0.0f; }
}
__global__ void deg_count(const int* __restrict__ adj) {
    int e = blockIdx.x * blockDim.x + threadIdx.x;
    if (e < EE) atomicAdd(&g_deg[adj[EE + e]], 1);
}
__global__ void __launch_bounds__(1024) scan_offsets() {
    __shared__ int partial[1024];
    const int tid = threadIdx.x;
    const int PER = (NN + 1023) / 1024;
    const int base = tid * PER;
    int s = 0;
#pragma unroll
    for (int i = 0; i < PER; i++) {
        int idx = base + i;
        if (idx < NN) s += g_deg[idx];
    }
    partial[tid] = s;
    __syncthreads();
    for (int off = 1; off < 1024; off <<= 1) {
        int v = 0;
        if (tid >= off) v = partial[tid - off];
        __syncthreads();
        if (tid >= off) partial[tid] += v;
        __syncthreads();
    }
    int run = (tid > 0) ? partial[tid - 1] : 0;
#pragma unroll
    for (int i = 0; i < PER; i++) {
        int idx = base + i;
        if (idx < NN) {
            g_off[idx] = run;
            int d = g_deg[idx];
            run += d;
            g_dinv[idx] = rsqrtf(1.0f + (float)d);
        }
    }
    if (tid == 0) g_off[NN] = EE;
}
__global__ void fill_csr(const int* __restrict__ adj) {
    int e = blockIdx.x * blockDim.x + threadIdx.x;
    if (e >= EE) return;
    int s = adj[e];
    int d = adj[EE + e];
    int pos = g_off[d] + atomicAdd(&g_cnt[d], 1);
    g_esrc[pos] = s;
}

// ---------------- row sums of Ek / Ev ----------------
__global__ void rowsums(const float* __restrict__ Ek, const float* __restrict__ Ev) {
    int gw = (blockIdx.x * blockDim.x + threadIdx.x) >> 5;
    int lane = threadIdx.x & 31;
    if (gw >= 2 * DC) return;
    const float* src = (gw < DC) ? Ek + (size_t)gw * NN : Ev + (size_t)(gw - DC) * NN;
    float s = 0.0f;
    for (int i = lane * 4; i < NN; i += 128) {
        float4 v = *(const float4*)(src + i);
        s += v.x + v.y + v.z + v.w;
    }
#pragma unroll
    for (int o = 16; o > 0; o >>= 1) s += __shfl_xor_sync(0xffffffffu, s, o);
    if (lane == 0) {
        if (gw < DC) g_rsk[gw] = s;
        else         g_rsv[gw - DC] = s;
    }
}

// ---------------- CSR gather + fused GCN finalize --------------------------
__global__ void __launch_bounds__(128) gcn_gather() {
    __shared__ int   s_src[128];
    __shared__ float s_coef[128];
    const int d = blockIdx.x;
    const int tid = threadIdx.x;
    const int beg = g_off[d];
    const int deg = g_off[d + 1] - beg;
    const float di = g_dinv[d];

    float4 acc = {0.f, 0.f, 0.f, 0.f};
    for (int c0 = 0; c0 < deg; c0 += 128) {
        int m = min(128, deg - c0);
        if (tid < m) {
            int s = g_esrc[beg + c0 + tid];
            s_src[tid] = s;
            s_coef[tid] = g_dinv[s] * di;
        }
        __syncthreads();
        int i = 0;
#pragma unroll 1
        for (; i + 4 <= m; i += 4) {
            const float4 h0 = *(const float4*)(g_h + (size_t)s_src[i + 0] * 512 + tid * 4);
            const float4 h1 = *(const float4*)(g_h + (size_t)s_src[i + 1] * 512 + tid * 4);
            const float4 h2 = *(const float4*)(g_h + (size_t)s_src[i + 2] * 512 + tid * 4);
            const float4 h3 = *(const float4*)(g_h + (size_t)s_src[i + 3] * 512 + tid * 4);
            float c0f = s_coef[i + 0], c1f = s_coef[i + 1];
            float c2f = s_coef[i + 2], c3f = s_coef[i + 3];
            acc.x += h0.x * c0f; acc.y += h0.y * c0f; acc.z += h0.z * c0f; acc.w += h0.w * c0f;
            acc.x += h1.x * c1f; acc.y += h1.y * c1f; acc.z += h1.z * c1f; acc.w += h1.w * c1f;
            acc.x += h2.x * c2f; acc.y += h2.y * c2f; acc.z += h2.z * c2f; acc.w += h2.w * c2f;
            acc.x += h3.x * c3f; acc.y += h3.y * c3f; acc.z += h3.z * c3f; acc.w += h3.w * c3f;
        }
        for (; i < m; i++) {
            const float4 hv = *(const float4*)(g_h + (size_t)s_src[i] * 512 + tid * 4);
            float cf = s_coef[i];
            acc.x += hv.x * cf; acc.y += hv.y * cf; acc.z += hv.z * cf; acc.w += hv.w * cf;
        }
        __syncthreads();
    }

    const int j = tid * 4;
    const float4 hd = *(const float4*)(g_h + (size_t)d * 512 + j);
    const float4 bb = *(const float4*)(g_b12 + j);
    const float d2 = di * di;
    float4 v;
    v.x = acc.x + hd.x * d2 + bb.x;
    v.y = acc.y + hd.y * d2 + bb.y;
    v.z = acc.z + hd.z * d2 + bb.z;
    v.w = acc.w + hd.w * d2 + bb.w;
    if (j < 256) {
        float4 o;
        o.x = 1.0f / (1.0f + __expf(-v.x));
        o.y = 1.0f / (1.0f + __expf(-v.y));
        o.z = 1.0f / (1.0f + __expf(-v.z));
        o.w = 1.0f / (1.0f + __expf(-v.w));
        *(float4*)(g_g1 + (size_t)d * 256 + j) = o;
    } else {
        *(float4*)(g_xa + (size_t)d * 256 + (j - 256)) = v;
    }
}

// ---------------- SGEMM (SIMT, peq only) ------------------------------------
template <int ACT>
__global__ void __launch_bounds__(256)
sgemm2(const float* __restrict__ A, const float* __restrict__ B,
       const float* __restrict__ bias, const float* __restrict__ rowscale,
       float* __restrict__ C, int M, int N, int K) {
    __shared__ float As[2][16][128];
    __shared__ float Bs[2][16][128];
    const int tid = threadIdx.x;
    const int rowBase = blockIdx.y * 128;
    const int colBase = blockIdx.x * 128;

    const int lr = tid >> 1;
    const int lq = (tid & 1) * 8;
    const int br = tid >> 5;
    const int bc = (tid & 31) * 4;
    const int rm = tid >> 4;
    const int rn = tid & 15;

    const int arow = rowBase + lr;
    const bool aval = arow < M;
    const float* Aptr = A + (size_t)arow * K + lq;
    const float* Bptr = B + colBase + bc;

    float acc[8][8];
#pragma unroll
    for (int i = 0; i < 8; i++)
#pragma unroll
        for (int j = 0; j < 8; j++) acc[i][j] = 0.0f;

    const int niter = K >> 4;
    float4 a0, a1, b0, b1;
    a0 = aval ? *(const float4*)(Aptr + 0) : make_float4(0, 0, 0, 0);
    a1 = aval ? *(const float4*)(Aptr + 4) : make_float4(0, 0, 0, 0);
    b0 = *(const float4*)(Bptr + (size_t)br * N);
    b1 = *(const float4*)(Bptr + (size_t)(br + 8) * N);
    As[0][lq + 0][lr] = a0.x; As[0][lq + 1][lr] = a0.y;
    As[0][lq + 2][lr] = a0.z; As[0][lq + 3][lr] = a0.w;
    As[0][lq + 4][lr] = a1.x; As[0][lq + 5][lr] = a1.y;
    As[0][lq + 6][lr] = a1.z; As[0][lq + 7][lr] = a1.w;
    *(float4*)&Bs[0][br][bc] = b0;
    *(float4*)&Bs[0][br + 8][bc] = b1;
    __syncthreads();

    for (int it = 0; it < niter; it++) {
        const int cur = it & 1;
        if (it + 1 < niter) {
            const int k0 = (it + 1) << 4;
            a0 = aval ? *(const float4*)(Aptr + k0) : make_float4(0, 0, 0, 0);
            a1 = aval ? *(const float4*)(Aptr + k0 + 4) : make_float4(0, 0, 0, 0);
            b0 = *(const float4*)(Bptr + (size_t)(k0 + br) * N);
            b1 = *(const float4*)(Bptr + (size_t)(k0 + br + 8) * N);
        }
#pragma unroll
        for (int k = 0; k < 16; k++) {
            float4 av0 = *(const float4*)&As[cur][k][rm * 8];
            float4 av1 = *(const float4*)&As[cur][k][rm * 8 + 4];
            float4 bv0 = *(const float4*)&Bs[cur][k][rn * 8];
            float4 bv1 = *(const float4*)&Bs[cur][k][rn * 8 + 4];
            float av[8] = {av0.x, av0.y, av0.z, av0.w, av1.x, av1.y, av1.z, av1.w};
            float bv[8] = {bv0.x, bv0.y, bv0.z, bv0.w, bv1.x, bv1.y, bv1.z, bv1.w};
#pragma unroll
            for (int i = 0; i < 8; i++)
#pragma unroll
                for (int j = 0; j < 8; j++) acc[i][j] += av[i] * bv[j];
        }
        if (it + 1 < niter) {
            const int nxt = cur ^ 1;
            As[nxt][lq + 0][lr] = a0.x; As[nxt][lq + 1][lr] = a0.y;
            As[nxt][lq + 2][lr] = a0.z; As[nxt][lq + 3][lr] = a0.w;
            As[nxt][lq + 4][lr] = a1.x; As[nxt][lq + 5][lr] = a1.y;
            As[nxt][lq + 6][lr] = a1.z; As[nxt][lq + 7][lr] = a1.w;
            *(float4*)&Bs[nxt][br][bc] = b0;
            *(float4*)&Bs[nxt][br + 8][bc] = b1;
        }
        __syncthreads();
    }

#pragma unroll
    for (int i = 0; i < 8; i++) {
        int row = rowBase + rm * 8 + i;
        if (row >= M) continue;
        float rsc = (ACT == 2) ? rowscale[row] : 1.0f;
        int col0 = colBase + rn * 8;
#pragma unroll
        for (int j4 = 0; j4 < 2; j4++) {
            float4 o;
            float* op = &o.x;
#pragma unroll
            for (int j = 0; j < 4; j++) {
                int jj = j4 * 4 + j;
                float v = acc[i][jj];
                if (bias) v += rsc * bias[col0 + jj];
                if (ACT == 1) v = (v >= 0.0f) ? v : 0.01f * v;
                op[j] = v;
            }
            *(float4*)&C[(size_t)row * N + col0 + j4 * 4] = o;
        }
    }
}

// ---------------- row norms of tfa / tga ----------------
__global__ void norms_kernel() {
    int n = blockIdx.x * blockDim.x + threadIdx.x;
    if (n >= NN) return;
    const float4* a = (const float4*)(g_ab + (size_t)n * 128);
    float sa = 0.0f, sb = 0.0f;
#pragma unroll
    for (int i = 0; i < 16; i++) {
        float4 v = a[i];
        sa += v.x * v.x + v.y * v.y + v.z * v.z + v.w * v.w;
    }
#pragma unroll
    for (int i = 16; i < 32; i++) {
        float4 v = a[i];
        sb += v.x * v.x + v.y * v.y + v.z * v.z + v.w * v.w;
    }
    g_na[n] = sqrtf(sa);
    g_nb[n] = sqrtf(sb);
}

// ---------------- final cosine for 200K pairs ----------------
__global__ void final_pairs(const int* __restrict__ ts, float* __restrict__ out) {
    int t = blockIdx.x * blockDim.x + threadIdx.x;
    if (t >= NT) return;
    int i = ts[2 * t];
    int j = ts[2 * t + 1];
    const float4* a = (const float4*)(g_ab + (size_t)i * 128);
    const float4* b = (const float4*)(g_ab + (size_t)j * 128 + 64);
    float dot = 0.0f;
#pragma unroll
    for (int p = 0; p < 16; p++) {
        float4 av = a[p];
        float4 bv = b[p];
        dot += av.x * bv.x + av.y * bv.y + av.z * bv.z + av.w * bv.w;
    }
    out[t] = dot / fmaxf(g_na[i] * g_nb[j], 1e-8f);
}

// ---------------- host launcher ----------------
static float* symaddr(const void* sym) {
    void* p = nullptr;
    cudaGetSymbolAddress(&p, sym);
    return (float*)p;
}

extern "C" void kernel_launch(void* const* d_in, const int* in_sizes, int n_in,
                              void* d_out, int out_size) {
    const int*   train_sample = (const int*)d_in[1];
    const float* data_feature = (const float*)d_in[2];
    const int*   adj          = (const int*)d_in[3];
    const int*   positions    = (const int*)d_in[4];
    const float* gcn_W   = (const float*)d_in[5];
    const float* gcn_b   = (const float*)d_in[6];
    const float* gcnA2_W = (const float*)d_in[7];
    const float* gcnA2_b = (const float*)d_in[8];
    const float* lin_W   = (const float*)d_in[9];
    const float* lin_b   = (const float*)d_in[10];
    const float* tf_W    = (const float*)d_in[11];
    const float* tf_b    = (const float*)d_in[12];
    const float* tg_W    = (const float*)d_in[13];
    const float* tg_b    = (const float*)d_in[14];
    const float* Wq = (const float*)d_in[15];
    const float* bq = (const float*)d_in[16];
    const float* Wk = (const float*)d_in[17];
    const float* bk = (const float*)d_in[18];
    const float* Wv = (const float*)d_in[19];
    const float* bv = (const float*)d_in[20];
    const float* Wo = (const float*)d_in[21];
    const float* bo = (const float*)d_in[22];
    const float* Ek = (const float*)d_in[23];
    const float* Ev = (const float*)d_in[24];
    const float* pos_emb = (const float*)d_in[25];
    const float* tfa_W = (const float*)d_in[26];
    const float* tfa_b = (const float*)d_in[27];
    const float* tga_W = (const float*)d_in[28];
    const float* tga_b = (const float*)d_in[29];

    float* d_lint  = symaddr(g_lint);
    float* d_tftgt = symaddr(g_tftgt);
    float* d_btftg = symaddr(g_btftg);
    float* d_Wqt   = symaddr(g_Wqt);
    float* d_Woabt = symaddr(g_Woabt);
    float* d_bab2  = symaddr(g_bab2);
    float* d_W12t  = symaddr(g_W12t);
    float* d_g1   = symaddr(g_g1);
    float* d_xa   = symaddr(g_xa);
    float* d_xg   = symaddr(g_xg);
    float* d_tftg = symaddr(g_tftg);
    float* d_q    = symaddr(g_q);
    float* d_peq  = symaddr(g_peq);
    float* d_att  = symaddr(g_att);
    float* d_ab   = symaddr(g_ab);
    float* d_h    = symaddr(g_h);

    // 1. merged weight packs + Wo@Wab fold (2 launches)
    pack_all<<<(PACK_TOTAL + 255) / 256, 256>>>(gcn_W, gcnA2_W, gcn_b, gcnA2_b,
                                                lin_W, tf_W, tg_W, tf_b, tg_b, Wq);
    fold_woab<<<(128 * 128 + 255) / 256, 256>>>(Wo, tfa_W, tga_W, bo, tfa_b, tga_b);

    // 2. CSR construction (deg_zero also zeroes kinc/vinc) + Ek/Ev row sums
    deg_zero<<<(DC * 128 + 255) / 256, 256>>>();
    deg_count<<<(EE + 255) / 256, 256>>>(adj);
    scan_offsets<<<1, 1024>>>();
    fill_csr<<<(EE + 255) / 256, 256>>>(adj);
    rowsums<<<(2 * DC * 32 + 255) / 256, 256>>>(Ek, Ev);

    // 3. h = data_feature @ [gcn_W | gcnA2_W]  — tf32 mma
    mma_gemm<0, 0><<<dim3(4, 157), 256>>>(data_feature, d_W12t, nullptr, d_h,
                                          NN, 512, 512, nullptr, nullptr);

    // 4. CSR gather + fused finalize -> g1 (sigmoid), xa
    gcn_gather<<<NN, 128>>>();

    // 5. x_g; [tf|tg] with fused kin = tf + pos_emb[pos]
    mma_gemm<1, 0><<<dim3(1, 157), 256>>>(d_g1, d_lint, lin_b, d_xg,
                                          NN, 128, 256, nullptr, nullptr);
    mma_gemm<1, 1><<<dim3(2, 157), 256>>>(d_xa, d_tftgt, d_btftg, d_tftg,
                                          NN, 256, 256, positions, pos_emb);

    // 6. q = xg@Wq + bq (mma); peq = pos_emb@Wq (SIMT, tiny)
    mma_gemm<0, 0><<<dim3(1, 157), 256>>>(d_xg, d_Wqt, bq, d_q,
                                          NN, 128, 128, nullptr, nullptr);
    sgemm2<0><<<dim3(1, 4), 256>>>(pos_emb, Wq, nullptr, nullptr, d_peq, 512, 128, 128);

    // 7. kinc/vinc: exact fp32 SIMT split-K; then one fused projection launch
    splitk_ckv<<<dim3(2, 4, 50), 256>>>(Ek, Ev);
    proj_ckv<<<dim3(1, 2, 2), 256>>>(Wk, bk, Wv, bv);

    // 8. scalar fp32 attention (proven fast + accurate)
    attn_kernel<<<dim3(157, 8), 128>>>(positions);

    // 9. ab = leaky(att @ (Wo@Wab) + bab2)  — folded, single tf32 mma
    mma_gemm<1, 0><<<dim3(1, 157), 256>>>(d_att, d_Woabt, d_bab2, d_ab,
                                          NN, 128, 128, nullptr, nullptr);

    // 10. norms + final cosine pairs
    norms_kernel<<<(NN + 255) / 256, 256>>>();
    final_pairs<<<(NT + 255) / 256, 256>>>(train_sample, (float*)d_out);
}

// round 17
// speedup vs baseline: 1.2663x; 1.1817x over previous
#include <cuda_runtime.h>
#include <math.h>
#include <stdint.h>

// ---------------- problem constants ----------------
constexpr int NN   = 20000;
constexpr int EE   = 320000;
constexpr int NT   = 200000;
constexpr int DC   = 256;

// ---------------- scratch (static device globals; no runtime alloc) --------
__device__ float g_W12t[512 * 512];        // transposed fused weights [n][k]
__device__ float g_b12[512];
__device__ float g_lint[128 * 256];        // lin_W^T
__device__ float g_tftgt[256 * 256];       // [tf_W | tg_W]^T
__device__ float g_btftg[256];
__device__ float g_Wqt[128 * 128];
__device__ float g_Woabt[128 * 128];       // (Wo @ [tfa_W|tga_W])^T
__device__ float g_bab2[128];              // bo@Wab + [tfa_b|tga_b]

__device__ float g_h[(size_t)NN * 512];    // [h_gcn1 | h_gcn2]
__device__ float g_dinv[NN];

__device__ int g_deg[NN];
__device__ int g_cnt[NN];
__device__ int g_off[NN + 1];
__device__ int g_esrc[EE];

__device__ float g_g1[(size_t)NN * 256];
__device__ float g_xa[(size_t)NN * 256];
__device__ float g_xg[(size_t)NN * 128];
__device__ float g_tftg[(size_t)NN * 256];

__device__ float g_kin[(size_t)NN * 128];
__device__ float g_q[(size_t)NN * 128];
__device__ float g_peq[512 * 128];

__device__ float g_kinc[DC * 128];
__device__ float g_vinc[DC * 128];
__device__ float g_rsk[DC];
__device__ float g_rsv[DC];
__device__ float g_kc[DC * 128];
__device__ float g_vc[DC * 128];

__device__ float g_att[(size_t)NN * 128];
__device__ float g_ab[(size_t)NN * 128];
__device__ float g_na[NN];
__device__ float g_nb[NN];

// ---------------- tf32 helpers ----------------
__device__ __forceinline__ uint32_t cvt_tf32(float f) {
    uint32_t u;
    asm("cvt.rna.tf32.f32 %0, %1;" : "=r"(u) : "f"(f));
    return u;
}
__device__ __forceinline__ uint4 cvt_tf32x4(float4 v) {
    uint4 r;
    r.x = cvt_tf32(v.x); r.y = cvt_tf32(v.y);
    r.z = cvt_tf32(v.z); r.w = cvt_tf32(v.w);
    return r;
}
#define MMA_TF32(c, a, b) \
    asm volatile( \
        "mma.sync.aligned.m16n8k8.row.col.f32.tf32.tf32.f32 " \
        "{%0,%1,%2,%3}, {%4,%5,%6,%7}, {%8,%9}, {%0,%1,%2,%3};" \
        : "+f"((c)[0]), "+f"((c)[1]), "+f"((c)[2]), "+f"((c)[3]) \
        : "r"((a)[0]), "r"((a)[1]), "r"((a)[2]), "r"((a)[3]), \
          "r"((b)[0]), "r"((b)[1]))

// ---------------- generic tf32 mma.sync GEMM: C = act(A@Bt^T + bias) -------
// BM=128, BN=128, BK=32. 256 threads = 8 warps; warp tile 64x32 (4x4 m16n8k8).
// ACT: 0 = none, 1 = leaky relu. KIN: also write g_kin for cols<128.
constexpr int SPAD = 36;
template <int ACT, int KIN>
__global__ void __launch_bounds__(256)
mma_gemm(const float* __restrict__ A, const float* __restrict__ Bt,
         const float* __restrict__ bias, float* __restrict__ C,
         int M, int N, int K,
         const int* __restrict__ positions, const float* __restrict__ pos_emb) {
    __shared__ uint32_t sA[128 * SPAD];
    __shared__ uint32_t sB[128 * SPAD];
    const int tid = threadIdx.x;
    const int lane = tid & 31, wid = tid >> 5;
    const int wr = wid >> 2, wc = wid & 3;
    const int gq = lane >> 2, tq = lane & 3;
    const int rowBase = blockIdx.y * 128;
    const int colBase = blockIdx.x * 128;

    float c[4][4][4];
#pragma unroll
    for (int mt = 0; mt < 4; mt++)
#pragma unroll
        for (int nt = 0; nt < 4; nt++)
#pragma unroll
            for (int r = 0; r < 4; r++) c[mt][nt][r] = 0.0f;

    int lrow[4], lc4[4];
#pragma unroll
    for (int p = 0; p < 4; p++) {
        int idx = tid + p * 256;
        lrow[p] = idx >> 3;
        lc4[p] = idx & 7;
    }

    uint4 ra[4], rb[4];
#pragma unroll
    for (int p = 0; p < 4; p++) {
        int arow = rowBase + lrow[p];
        float4 av = (arow < M)
            ? *(const float4*)(A + (size_t)arow * K + lc4[p] * 4)
            : make_float4(0.f, 0.f, 0.f, 0.f);
        ra[p] = cvt_tf32x4(av);
        float4 bv = *(const float4*)(Bt + (size_t)(colBase + lrow[p]) * K + lc4[p] * 4);
        rb[p] = cvt_tf32x4(bv);
    }
#pragma unroll
    for (int p = 0; p < 4; p++) {
        *(uint4*)&sA[lrow[p] * SPAD + lc4[p] * 4] = ra[p];
        *(uint4*)&sB[lrow[p] * SPAD + lc4[p] * 4] = rb[p];
    }
    __syncthreads();

    const int niter = K >> 5;
    for (int it = 0; it < niter; it++) {
        if (it + 1 < niter) {
            const int k0 = (it + 1) * 32;
#pragma unroll
            for (int p = 0; p < 4; p++) {
                int arow = rowBase + lrow[p];
                float4 av = (arow < M)
                    ? *(const float4*)(A + (size_t)arow * K + k0 + lc4[p] * 4)
                    : make_float4(0.f, 0.f, 0.f, 0.f);
                ra[p] = cvt_tf32x4(av);
                float4 bv = *(const float4*)(Bt + (size_t)(colBase + lrow[p]) * K + k0 + lc4[p] * 4);
                rb[p] = cvt_tf32x4(bv);
            }
        }
#pragma unroll
        for (int ks = 0; ks < 4; ks++) {
            const int kb = ks * 8 + tq;
            uint32_t af[4][4];
#pragma unroll
            for (int mt = 0; mt < 4; mt++) {
                int base = (wr * 64 + mt * 16 + gq) * SPAD + kb;
                af[mt][0] = sA[base];
                af[mt][1] = sA[base + 8 * SPAD];
                af[mt][2] = sA[base + 4];
                af[mt][3] = sA[base + 8 * SPAD + 4];
            }
            uint32_t bf[4][2];
#pragma unroll
            for (int nt = 0; nt < 4; nt++) {
                int base = (wc * 32 + nt * 8 + gq) * SPAD + kb;
                bf[nt][0] = sB[base];
                bf[nt][1] = sB[base + 4];
            }
#pragma unroll
            for (int mt = 0; mt < 4; mt++)
#pragma unroll
                for (int nt = 0; nt < 4; nt++)
                    MMA_TF32(c[mt][nt], af[mt], bf[nt]);
        }
        __syncthreads();
        if (it + 1 < niter) {
#pragma unroll
            for (int p = 0; p < 4; p++) {
                *(uint4*)&sA[lrow[p] * SPAD + lc4[p] * 4] = ra[p];
                *(uint4*)&sB[lrow[p] * SPAD + lc4[p] * 4] = rb[p];
            }
            __syncthreads();
        }
    }

#pragma unroll
    for (int mt = 0; mt < 4; mt++) {
        int row0 = rowBase + wr * 64 + mt * 16 + gq;
#pragma unroll
        for (int nt = 0; nt < 4; nt++) {
            int col = colBase + wc * 32 + nt * 8 + tq * 2;
            float b0 = 0.f, b1 = 0.f;
            if (bias) {
                float2 bb = *(const float2*)(bias + col);
                b0 = bb.x; b1 = bb.y;
            }
            float v0 = c[mt][nt][0] + b0, v1 = c[mt][nt][1] + b1;
            float v2 = c[mt][nt][2] + b0, v3 = c[mt][nt][3] + b1;
            if (ACT == 1) {
                v0 = (v0 >= 0.f) ? v0 : 0.01f * v0;
                v1 = (v1 >= 0.f) ? v1 : 0.01f * v1;
                v2 = (v2 >= 0.f) ? v2 : 0.01f * v2;
                v3 = (v3 >= 0.f) ? v3 : 0.01f * v3;
            }
            if (row0 < M) {
                float2 o = { v0, v1 };
                *(float2*)(C + (size_t)row0 * N + col) = o;
                if (KIN && col < 128) {
                    float2 pe = *(const float2*)(pos_emb + (size_t)positions[row0] * 128 + col);
                    float2 kk = { v0 + pe.x, v1 + pe.y };
                    *(float2*)(g_kin + (size_t)row0 * 128 + col) = kk;
                }
            }
            if (row0 + 8 < M) {
                float2 o = { v2, v3 };
                *(float2*)(C + (size_t)(row0 + 8) * N + col) = o;
                if (KIN && col < 128) {
                    float2 pe = *(const float2*)(pos_emb + (size_t)positions[row0 + 8] * 128 + col);
                    float2 kk = { v2 + pe.x, v3 + pe.y };
                    *(float2*)(g_kin + (size_t)(row0 + 8) * 128 + col) = kk;
                }
            }
        }
    }
}

// ---------------- split-K SIMT fp32 GEMM: kinc = Ek@kin, vinc = Ev@tg ------
__global__ void __launch_bounds__(256)
splitk_ckv(const float* __restrict__ Ekm, const float* __restrict__ Evm) {
    const int mat = blockIdx.z & 1;
    const int split = blockIdx.z >> 1;
    const float* Am = mat ? Evm : Ekm;
    const float* Xm = mat ? (g_tftg + 128) : g_kin;
    const int ldb = mat ? 256 : 128;
    float* Cm = mat ? g_vinc : g_kinc;

    const int rowBase = blockIdx.y * 64;
    const int colBase = blockIdx.x * 64;
    const int tid = threadIdx.x;
    const int rm = tid >> 4, rn = tid & 15;

    __shared__ float As[32][64];
    __shared__ float Bs[32][64];

    float acc[4][4];
#pragma unroll
    for (int i = 0; i < 4; i++)
#pragma unroll
        for (int j = 0; j < 4; j++) acc[i][j] = 0.0f;

    const int kstart = split * 25 * 32;
    for (int it = 0; it < 25; it++) {
        int kbase = kstart + it * 32;
        __syncthreads();
#pragma unroll
        for (int pp = 0; pp < 2; pp++) {
            int p = tid + pp * 256;
            int row = p >> 3;
            int kq = (p & 7) * 4;
            float4 a4 = *(const float4*)(Am + (size_t)(rowBase + row) * NN + kbase + kq);
            As[kq + 0][row] = a4.x;
            As[kq + 1][row] = a4.y;
            As[kq + 2][row] = a4.z;
            As[kq + 3][row] = a4.w;
            int krow = p >> 4;
            int cq = (p & 15) * 4;
            float4 b4 = *(const float4*)(Xm + (size_t)(kbase + krow) * ldb + colBase + cq);
            *(float4*)&Bs[krow][cq] = b4;
        }
        __syncthreads();
#pragma unroll
        for (int k = 0; k < 32; k++) {
            float4 a4 = *(float4*)&As[k][rm * 4];
            float4 b4 = *(float4*)&Bs[k][rn * 4];
            float av[4] = {a4.x, a4.y, a4.z, a4.w};
            float bv[4] = {b4.x, b4.y, b4.z, b4.w};
#pragma unroll
            for (int i = 0; i < 4; i++)
#pragma unroll
                for (int j = 0; j < 4; j++) acc[i][j] += av[i] * bv[j];
        }
    }
#pragma unroll
    for (int i = 0; i < 4; i++)
#pragma unroll
        for (int j = 0; j < 4; j++)
            atomicAdd(&Cm[(size_t)(rowBase + rm * 4 + i) * 128 + colBase + rn * 4 + j],
                      acc[i][j]);
}

// ---------------- fused kc/vc projection (one launch, z selects matrix) ----
__global__ void __launch_bounds__(256)
proj_ckv(const float* __restrict__ Wk, const float* __restrict__ bk,
         const float* __restrict__ Wv, const float* __restrict__ bv) {
    const int mat = blockIdx.z;
    const float* A = mat ? g_vinc : g_kinc;
    const float* B = mat ? Wv : Wk;
    const float* bias = mat ? bv : bk;
    const float* rowscale = mat ? g_rsv : g_rsk;
    float* C = mat ? g_vc : g_kc;
    const int M = 256, N = 128, K = 128;

    __shared__ float As[2][16][128];
    __shared__ float Bs[2][16][128];
    const int tid = threadIdx.x;
    const int rowBase = blockIdx.y * 128;

    const int lr = tid >> 1;
    const int lq = (tid & 1) * 8;
    const int br = tid >> 5;
    const int bc = (tid & 31) * 4;
    const int rm = tid >> 4;
    const int rn = tid & 15;

    const float* Aptr = A + (size_t)(rowBase + lr) * K + lq;
    const float* Bptr = B + bc;

    float acc[8][8];
#pragma unroll
    for (int i = 0; i < 8; i++)
#pragma unroll
        for (int j = 0; j < 8; j++) acc[i][j] = 0.0f;

    const int niter = K >> 4;
    float4 a0, a1, b0, b1;
    a0 = *(const float4*)(Aptr + 0);
    a1 = *(const float4*)(Aptr + 4);
    b0 = *(const float4*)(Bptr + (size_t)br * N);
    b1 = *(const float4*)(Bptr + (size_t)(br + 8) * N);
    As[0][lq + 0][lr] = a0.x; As[0][lq + 1][lr] = a0.y;
    As[0][lq + 2][lr] = a0.z; As[0][lq + 3][lr] = a0.w;
    As[0][lq + 4][lr] = a1.x; As[0][lq + 5][lr] = a1.y;
    As[0][lq + 6][lr] = a1.z; As[0][lq + 7][lr] = a1.w;
    *(float4*)&Bs[0][br][bc] = b0;
    *(float4*)&Bs[0][br + 8][bc] = b1;
    __syncthreads();

    for (int it = 0; it < niter; it++) {
        const int cur = it & 1;
        if (it + 1 < niter) {
            const int k0 = (it + 1) << 4;
            a0 = *(const float4*)(Aptr + k0);
            a1 = *(const float4*)(Aptr + k0 + 4);
            b0 = *(const float4*)(Bptr + (size_t)(k0 + br) * N);
            b1 = *(const float4*)(Bptr + (size_t)(k0 + br + 8) * N);
        }
#pragma unroll
        for (int k = 0; k < 16; k++) {
            float4 av0 = *(const float4*)&As[cur][k][rm * 8];
            float4 av1 = *(const float4*)&As[cur][k][rm * 8 + 4];
            float4 bv0 = *(const float4*)&Bs[cur][k][rn * 8];
            float4 bv1 = *(const float4*)&Bs[cur][k][rn * 8 + 4];
            float av[8] = {av0.x, av0.y, av0.z, av0.w, av1.x, av1.y, av1.z, av1.w};
            float bvv[8] = {bv0.x, bv0.y, bv0.z, bv0.w, bv1.x, bv1.y, bv1.z, bv1.w};
#pragma unroll
            for (int i = 0; i < 8; i++)
#pragma unroll
                for (int j = 0; j < 8; j++) acc[i][j] += av[i] * bvv[j];
        }
        if (it + 1 < niter) {
            const int nxt = cur ^ 1;
            As[nxt][lq + 0][lr] = a0.x; As[nxt][lq + 1][lr] = a0.y;
            As[nxt][lq + 2][lr] = a0.z; As[nxt][lq + 3][lr] = a0.w;
            As[nxt][lq + 4][lr] = a1.x; As[nxt][lq + 5][lr] = a1.y;
            As[nxt][lq + 6][lr] = a1.z; As[nxt][lq + 7][lr] = a1.w;
            *(float4*)&Bs[nxt][br][bc] = b0;
            *(float4*)&Bs[nxt][br + 8][bc] = b1;
        }
        __syncthreads();
    }

#pragma unroll
    for (int i = 0; i < 8; i++) {
        int row = rowBase + rm * 8 + i;
        float rsc = rowscale[row];
        int col0 = rn * 8;
#pragma unroll
        for (int j4 = 0; j4 < 2; j4++) {
            float4 o;
            float* op = &o.x;
#pragma unroll
            for (int j = 0; j < 4; j++) {
                int jj = j4 * 4 + j;
                op[j] = acc[i][jj] + rsc * bias[col0 + jj];
            }
            *(float4*)&C[(size_t)row * N + col0 + j4 * 4] = o;
        }
    }
}

// ---------------- scalar fused attention (fp32, proven) --------------------
__global__ void __launch_bounds__(128)
attn_kernel(const int* __restrict__ positions) {
    __shared__ float4 kcs[DC][4];
    __shared__ float4 vcs[DC][4];
    const int h = blockIdx.y;
    const int tid = threadIdx.x;
    for (int p = tid; p < DC * 4; p += 128) {
        int c = p >> 2, d = p & 3;
        kcs[c][d] = *(const float4*)(g_kc + c * 128 + h * 16 + d * 4);
        vcs[c][d] = *(const float4*)(g_vc + c * 128 + h * 16 + d * 4);
    }
    __syncthreads();
    int n = blockIdx.x * 128 + tid;
    if (n >= NN) return;

    const int pos = positions[n];
    const float* qp = g_q + (size_t)n * 128 + h * 16;
    const float* pp = g_peq + (size_t)pos * 128 + h * 16;
    float4 q0 = *(const float4*)(qp + 0);
    float4 q1 = *(const float4*)(qp + 4);
    float4 q2 = *(const float4*)(qp + 8);
    float4 q3 = *(const float4*)(qp + 12);
    float4 p0 = *(const float4*)(pp + 0);
    float4 p1 = *(const float4*)(pp + 4);
    float4 p2 = *(const float4*)(pp + 8);
    float4 p3 = *(const float4*)(pp + 12);
    q0.x += p0.x; q0.y += p0.y; q0.z += p0.z; q0.w += p0.w;
    q1.x += p1.x; q1.y += p1.y; q1.z += p1.z; q1.w += p1.w;
    q2.x += p2.x; q2.y += p2.y; q2.z += p2.z; q2.w += p2.w;
    q3.x += p3.x; q3.y += p3.y; q3.z += p3.z; q3.w += p3.w;

    float s = 0.0f;
    float4 o0 = {0, 0, 0, 0}, o1 = {0, 0, 0, 0}, o2 = {0, 0, 0, 0}, o3 = {0, 0, 0, 0};

    for (int c = 0; c < DC; c++) {
        float4 k0 = kcs[c][0], k1 = kcs[c][1], k2 = kcs[c][2], k3 = kcs[c][3];
        float dot = q0.x * k0.x + q0.y * k0.y + q0.z * k0.z + q0.w * k0.w
                  + q1.x * k1.x + q1.y * k1.y + q1.z * k1.z + q1.w * k1.w
                  + q2.x * k2.x + q2.y * k2.y + q2.z * k2.z + q2.w * k2.w
                  + q3.x * k3.x + q3.y * k3.y + q3.z * k3.z + q3.w * k3.w;
        float p = __expf(dot * 0.25f);
        s += p;
        float4 v0 = vcs[c][0], v1 = vcs[c][1], v2 = vcs[c][2], v3 = vcs[c][3];
        o0.x += p * v0.x; o0.y += p * v0.y; o0.z += p * v0.z; o0.w += p * v0.w;
        o1.x += p * v1.x; o1.y += p * v1.y; o1.z += p * v1.z; o1.w += p * v1.w;
        o2.x += p * v2.x; o2.y += p * v2.y; o2.z += p * v2.z; o2.w += p * v2.w;
        o3.x += p * v3.x; o3.y += p * v3.y; o3.z += p * v3.z; o3.w += p * v3.w;
    }
    float inv = 1.0f / s;
    float* op = g_att + (size_t)n * 128 + h * 16;
    o0.x *= inv; o0.y *= inv; o0.z *= inv; o0.w *= inv;
    o1.x *= inv; o1.y *= inv; o1.z *= inv; o1.w *= inv;
    o2.x *= inv; o2.y *= inv; o2.z *= inv; o2.w *= inv;
    o3.x *= inv; o3.y *= inv; o3.z *= inv; o3.w *= inv;
    *(float4*)(op + 0) = o0;
    *(float4*)(op + 4) = o1;
    *(float4*)(op + 8) = o2;
    *(float4*)(op + 12) = o3;
}

// ---------------- merged weight packs (one launch) --------------------------
__global__ void pack_all(const float* __restrict__ gcn_W, const float* __restrict__ gcnA2_W,
                         const float* __restrict__ gcn_b, const float* __restrict__ gcnA2_b,
                         const float* __restrict__ lin_W,
                         const float* __restrict__ tf_W, const float* __restrict__ tg_W,
                         const float* __restrict__ tf_b, const float* __restrict__ tg_b,
                         const float* __restrict__ Wq) {
    int idx = blockIdx.x * blockDim.x + threadIdx.x;
    if (idx < 512 * 512) {
        int n = idx >> 9, k = idx & 511;
        g_W12t[idx] = (n < 256) ? gcn_W[k * 256 + n] : gcnA2_W[k * 256 + (n - 256)];
        if (idx < 512) g_b12[idx] = (idx < 256) ? gcn_b[idx] : gcnA2_b[idx - 256];
        return;
    }
    int r = idx - 512 * 512;
    if (r < 128 * 256) {
        int n = r >> 8, k = r & 255;
        g_lint[r] = lin_W[k * 128 + n];
        return;
    }
    r -= 128 * 256;
    if (r < 256 * 256) {
        int n = r >> 8, k = r & 255;
        g_tftgt[r] = (n < 128) ? tf_W[k * 128 + n] : tg_W[k * 128 + (n - 128)];
        if (r < 256) g_btftg[r] = (r < 128) ? tf_b[r] : tg_b[r - 128];
        return;
    }
    r -= 256 * 256;
    if (r < 128 * 128) {
        int n = r >> 7, k = r & 127;
        g_Wqt[r] = Wq[k * 128 + n];
    }
}
constexpr int PACK_TOTAL = 512 * 512 + 128 * 256 + 256 * 256 + 128 * 128;

// fold: Woabt[n][k] = sum_j Wo[k][j] * Wab[j][n]; bab2[n] = bab[n] + sum_j bo[j]*Wab[j][n]
__global__ void fold_woab(const float* __restrict__ Wo,
                          const float* __restrict__ tfa_W, const float* __restrict__ tga_W,
                          const float* __restrict__ bo,
                          const float* __restrict__ tfa_b, const float* __restrict__ tga_b) {
    int idx = blockIdx.x * blockDim.x + threadIdx.x;
    if (idx < 128 * 128) {
        int n = idx >> 7, k = idx & 127;
        float s = 0.f;
        for (int j = 0; j < 128; j++) {
            float wab = (n < 64) ? tfa_W[j * 64 + n] : tga_W[j * 64 + (n - 64)];
            s += Wo[k * 128 + j] * wab;
        }
        g_Woabt[n * 128 + k] = s;
    }
    if (idx < 128) {
        int n = idx;
        float s = (n < 64) ? tfa_b[n] : tga_b[n - 64];
        for (int j = 0; j < 128; j++) {
            float wab = (n < 64) ? tfa_W[j * 64 + n] : tga_W[j * 64 + (n - 64)];
            s += bo[j] * wab;
        }
        g_bab2[n] = s;
    }
}

// ---------------- CSR construction (deg_zero also zeroes kinc/vinc) --------
__global__ void deg_zero() {
    int i = blockIdx.x * blockDim.x + threadIdx.x;
    if (i < NN) { g_deg[i] = 0; g_cnt[i] = 0; }
    if (i < DC * 128) { g_kinc[i] = 0.0f; g_vinc[i] = 0.0f; }
}
__global__ void deg_count(const int* __restrict__ adj) {
    int e = blockIdx.x * blockDim.x + threadIdx.x;
    if (e < EE) atomicAdd(&g_deg[adj[EE + e]], 1);
}
__global__ void __launch_bounds__(1024) scan_offsets() {
    __shared__ int partial[1024];
    const int tid = threadIdx.x;
    const int PER = (NN + 1023) / 1024;
    const int base = tid * PER;
    int s = 0;
#pragma unroll
    for (int i = 0; i < PER; i++) {
        int idx = base + i;
        if (idx < NN) s += g_deg[idx];
    }
    partial[tid] = s;
    __syncthreads();
    for (int off = 1; off < 1024; off <<= 1) {
        int v = 0;
        if (tid >= off) v = partial[tid - off];
        __syncthreads();
        if (tid >= off) partial[tid] += v;
        __syncthreads();
    }
    int run = (tid > 0) ? partial[tid - 1] : 0;
#pragma unroll
    for (int i = 0; i < PER; i++) {
        int idx = base + i;
        if (idx < NN) {
            g_off[idx] = run;
            int d = g_deg[idx];
            run += d;
            g_dinv[idx] = rsqrtf(1.0f + (float)d);
        }
    }
    if (tid == 0) g_off[NN] = EE;
}
__global__ void fill_csr(const int* __restrict__ adj) {
    int e = blockIdx.x * blockDim.x + threadIdx.x;
    if (e >= EE) return;
    int s = adj[e];
    int d = adj[EE + e];
    int pos = g_off[d] + atomicAdd(&g_cnt[d], 1);
    g_esrc[pos] = s;
}

// ---------------- row sums of Ek / Ev ----------------
__global__ void rowsums(const float* __restrict__ Ek, const float* __restrict__ Ev) {
    int gw = (blockIdx.x * blockDim.x + threadIdx.x) >> 5;
    int lane = threadIdx.x & 31;
    if (gw >= 2 * DC) return;
    const float* src = (gw < DC) ? Ek + (size_t)gw * NN : Ev + (size_t)(gw - DC) * NN;
    float s = 0.0f;
    for (int i = lane * 4; i < NN; i += 128) {
        float4 v = *(const float4*)(src + i);
        s += v.x + v.y + v.z + v.w;
    }
#pragma unroll
    for (int o = 16; o > 0; o >>= 1) s += __shfl_xor_sync(0xffffffffu, s, o);
    if (lane == 0) {
        if (gw < DC) g_rsk[gw] = s;
        else         g_rsv[gw - DC] = s;
    }
}

// ---------------- CSR gather + fused GCN finalize --------------------------
__global__ void __launch_bounds__(128) gcn_gather() {
    __shared__ int   s_src[128];
    __shared__ float s_coef[128];
    const int d = blockIdx.x;
    const int tid = threadIdx.x;
    const int beg = g_off[d];
    const int deg = g_off[d + 1] - beg;
    const float di = g_dinv[d];

    float4 acc = {0.f, 0.f, 0.f, 0.f};
    for (int c0 = 0; c0 < deg; c0 += 128) {
        int m = min(128, deg - c0);
        if (tid < m) {
            int s = g_esrc[beg + c0 + tid];
            s_src[tid] = s;
            s_coef[tid] = g_dinv[s] * di;
        }
        __syncthreads();
        int i = 0;
#pragma unroll 1
        for (; i + 4 <= m; i += 4) {
            const float4 h0 = *(const float4*)(g_h + (size_t)s_src[i + 0] * 512 + tid * 4);
            const float4 h1 = *(const float4*)(g_h + (size_t)s_src[i + 1] * 512 + tid * 4);
            const float4 h2 = *(const float4*)(g_h + (size_t)s_src[i + 2] * 512 + tid * 4);
            const float4 h3 = *(const float4*)(g_h + (size_t)s_src[i + 3] * 512 + tid * 4);
            float c0f = s_coef[i + 0], c1f = s_coef[i + 1];
            float c2f = s_coef[i + 2], c3f = s_coef[i + 3];
            acc.x += h0.x * c0f; acc.y += h0.y * c0f; acc.z += h0.z * c0f; acc.w += h0.w * c0f;
            acc.x += h1.x * c1f; acc.y += h1.y * c1f; acc.z += h1.z * c1f; acc.w += h1.w * c1f;
            acc.x += h2.x * c2f; acc.y += h2.y * c2f; acc.z += h2.z * c2f; acc.w += h2.w * c2f;
            acc.x += h3.x * c3f; acc.y += h3.y * c3f; acc.z += h3.z * c3f; acc.w += h3.w * c3f;
        }
        for (; i < m; i++) {
            const float4 hv = *(const float4*)(g_h + (size_t)s_src[i] * 512 + tid * 4);
            float cf = s_coef[i];
            acc.x += hv.x * cf; acc.y += hv.y * cf; acc.z += hv.z * cf; acc.w += hv.w * cf;
        }
        __syncthreads();
    }

    const int j = tid * 4;
    const float4 hd = *(const float4*)(g_h + (size_t)d * 512 + j);
    const float4 bb = *(const float4*)(g_b12 + j);
    const float d2 = di * di;
    float4 v;
    v.x = acc.x + hd.x * d2 + bb.x;
    v.y = acc.y + hd.y * d2 + bb.y;
    v.z = acc.z + hd.z * d2 + bb.z;
    v.w = acc.w + hd.w * d2 + bb.w;
    if (j < 256) {
        float4 o;
        o.x = 1.0f / (1.0f + __expf(-v.x));
        o.y = 1.0f / (1.0f + __expf(-v.y));
        o.z = 1.0f / (1.0f + __expf(-v.z));
        o.w = 1.0f / (1.0f + __expf(-v.w));
        *(float4*)(g_g1 + (size_t)d * 256 + j) = o;
    } else {
        *(float4*)(g_xa + (size_t)d * 256 + (j - 256)) = v;
    }
}

// ---------------- SGEMM (SIMT, peq only) ------------------------------------
template <int ACT>
__global__ void __launch_bounds__(256)
sgemm2(const float* __restrict__ A, const float* __restrict__ B,
       const float* __restrict__ bias, const float* __restrict__ rowscale,
       float* __restrict__ C, int M, int N, int K) {
    __shared__ float As[2][16][128];
    __shared__ float Bs[2][16][128];
    const int tid = threadIdx.x;
    const int rowBase = blockIdx.y * 128;
    const int colBase = blockIdx.x * 128;

    const int lr = tid >> 1;
    const int lq = (tid & 1) * 8;
    const int br = tid >> 5;
    const int bc = (tid & 31) * 4;
    const int rm = tid >> 4;
    const int rn = tid & 15;

    const int arow = rowBase + lr;
    const bool aval = arow < M;
    const float* Aptr = A + (size_t)arow * K + lq;
    const float* Bptr = B + colBase + bc;

    float acc[8][8];
#pragma unroll
    for (int i = 0; i < 8; i++)
#pragma unroll
        for (int j = 0; j < 8; j++) acc[i][j] = 0.0f;

    const int niter = K >> 4;
    float4 a0, a1, b0, b1;
    a0 = aval ? *(const float4*)(Aptr + 0) : make_float4(0, 0, 0, 0);
    a1 = aval ? *(const float4*)(Aptr + 4) : make_float4(0, 0, 0, 0);
    b0 = *(const float4*)(Bptr + (size_t)br * N);
    b1 = *(const float4*)(Bptr + (size_t)(br + 8) * N);
    As[0][lq + 0][lr] = a0.x; As[0][lq + 1][lr] = a0.y;
    As[0][lq + 2][lr] = a0.z; As[0][lq + 3][lr] = a0.w;
    As[0][lq + 4][lr] = a1.x; As[0][lq + 5][lr] = a1.y;
    As[0][lq + 6][lr] = a1.z; As[0][lq + 7][lr] = a1.w;
    *(float4*)&Bs[0][br][bc] = b0;
    *(float4*)&Bs[0][br + 8][bc] = b1;
    __syncthreads();

    for (int it = 0; it < niter; it++) {
        const int cur = it & 1;
        if (it + 1 < niter) {
            const int k0 = (it + 1) << 4;
            a0 = aval ? *(const float4*)(Aptr + k0) : make_float4(0, 0, 0, 0);
            a1 = aval ? *(const float4*)(Aptr + k0 + 4) : make_float4(0, 0, 0, 0);
            b0 = *(const float4*)(Bptr + (size_t)(k0 + br) * N);
            b1 = *(const float4*)(Bptr + (size_t)(k0 + br + 8) * N);
        }
#pragma unroll
        for (int k = 0; k < 16; k++) {
            float4 av0 = *(const float4*)&As[cur][k][rm * 8];
            float4 av1 = *(const float4*)&As[cur][k][rm * 8 + 4];
            float4 bv0 = *(const float4*)&Bs[cur][k][rn * 8];
            float4 bv1 = *(const float4*)&Bs[cur][k][rn * 8 + 4];
            float av[8] = {av0.x, av0.y, av0.z, av0.w, av1.x, av1.y, av1.z, av1.w};
            float bv[8] = {bv0.x, bv0.y, bv0.z, bv0.w, bv1.x, bv1.y, bv1.z, bv1.w};
#pragma unroll
            for (int i = 0; i < 8; i++)
#pragma unroll
                for (int j = 0; j < 8; j++) acc[i][j] += av[i] * bv[j];
        }
        if (it + 1 < niter) {
            const int nxt = cur ^ 1;
            As[nxt][lq + 0][lr] = a0.x; As[nxt][lq + 1][lr] = a0.y;
            As[nxt][lq + 2][lr] = a0.z; As[nxt][lq + 3][lr] = a0.w;
            As[nxt][lq + 4][lr] = a1.x; As[nxt][lq + 5][lr] = a1.y;
            As[nxt][lq + 6][lr] = a1.z; As[nxt][lq + 7][lr] = a1.w;
            *(float4*)&Bs[nxt][br][bc] = b0;
            *(float4*)&Bs[nxt][br + 8][bc] = b1;
        }
        __syncthreads();
    }

#pragma unroll
    for (int i = 0; i < 8; i++) {
        int row = rowBase + rm * 8 + i;
        if (row >= M) continue;
        float rsc = (ACT == 2) ? rowscale[row] : 1.0f;
        int col0 = colBase + rn * 8;
#pragma unroll
        for (int j4 = 0; j4 < 2; j4++) {
            float4 o;
            float* op = &o.x;
#pragma unroll
            for (int j = 0; j < 4; j++) {
                int jj = j4 * 4 + j;
                float v = acc[i][jj];
                if (bias) v += rsc * bias[col0 + jj];
                if (ACT == 1) v = (v >= 0.0f) ? v : 0.01f * v;
                op[j] = v;
            }
            *(float4*)&C[(size_t)row * N + col0 + j4 * 4] = o;
        }
    }
}

// ---------------- row norms of tfa / tga ----------------
__global__ void norms_kernel() {
    int n = blockIdx.x * blockDim.x + threadIdx.x;
    if (n >= NN) return;
    const float4* a = (const float4*)(g_ab + (size_t)n * 128);
    float sa = 0.0f, sb = 0.0f;
#pragma unroll
    for (int i = 0; i < 16; i++) {
        float4 v = a[i];
        sa += v.x * v.x + v.y * v.y + v.z * v.z + v.w * v.w;
    }
#pragma unroll
    for (int i = 16; i < 32; i++) {
        float4 v = a[i];
        sb += v.x * v.x + v.y * v.y + v.z * v.z + v.w * v.w;
    }
    g_na[n] = sqrtf(sa);
    g_nb[n] = sqrtf(sb);
}

// ---------------- final cosine for 200K pairs ----------------
__global__ void final_pairs(const int* __restrict__ ts, float* __restrict__ out) {
    int t = blockIdx.x * blockDim.x + threadIdx.x;
    if (t >= NT) return;
    int i = ts[2 * t];
    int j = ts[2 * t + 1];
    const float4* a = (const float4*)(g_ab + (size_t)i * 128);
    const float4* b = (const float4*)(g_ab + (size_t)j * 128 + 64);
    float dot = 0.0f;
#pragma unroll
    for (int p = 0; p < 16; p++) {
        float4 av = a[p];
        float4 bv = b[p];
        dot += av.x * bv.x + av.y * bv.y + av.z * bv.z + av.w * bv.w;
    }
    out[t] = dot / fmaxf(g_na[i] * g_nb[j], 1e-8f);
}

// ---------------- host launcher ----------------
static float* symaddr(const void* sym) {
    void* p = nullptr;
    cudaGetSymbolAddress(&p, sym);
    return (float*)p;
}

extern "C" void kernel_launch(void* const* d_in, const int* in_sizes, int n_in,
                              void* d_out, int out_size) {
    const int*   train_sample = (const int*)d_in[1];
    const float* data_feature = (const float*)d_in[2];
    const int*   adj          = (const int*)d_in[3];
    const int*   positions    = (const int*)d_in[4];
    const float* gcn_W   = (const float*)d_in[5];
    const float* gcn_b   = (const float*)d_in[6];
    const float* gcnA2_W = (const float*)d_in[7];
    const float* gcnA2_b = (const float*)d_in[8];
    const float* lin_W   = (const float*)d_in[9];
    const float* lin_b   = (const float*)d_in[10];
    const float* tf_W    = (const float*)d_in[11];
    const float* tf_b    = (const float*)d_in[12];
    const float* tg_W    = (const float*)d_in[13];
    const float* tg_b    = (const float*)d_in[14];
    const float* Wq = (const float*)d_in[15];
    const float* bq = (const float*)d_in[16];
    const float* Wk = (const float*)d_in[17];
    const float* bk = (const float*)d_in[18];
    const float* Wv = (const float*)d_in[19];
    const float* bv = (const float*)d_in[20];
    const float* Wo = (const float*)d_in[21];
    const float* bo = (const float*)d_in[22];
    const float* Ek = (const float*)d_in[23];
    const float* Ev = (const float*)d_in[24];
    const float* pos_emb = (const float*)d_in[25];
    const float* tfa_W = (const float*)d_in[26];
    const float* tfa_b = (const float*)d_in[27];
    const float* tga_W = (const float*)d_in[28];
    const float* tga_b = (const float*)d_in[29];

    float* d_lint  = symaddr(g_lint);
    float* d_tftgt = symaddr(g_tftgt);
    float* d_btftg = symaddr(g_btftg);
    float* d_Wqt   = symaddr(g_Wqt);
    float* d_Woabt = symaddr(g_Woabt);
    float* d_bab2  = symaddr(g_bab2);
    float* d_W12t  = symaddr(g_W12t);
    float* d_g1   = symaddr(g_g1);
    float* d_xa   = symaddr(g_xa);
    float* d_xg   = symaddr(g_xg);
    float* d_tftg = symaddr(g_tftg);
    float* d_q    = symaddr(g_q);
    float* d_peq  = symaddr(g_peq);
    float* d_att  = symaddr(g_att);
    float* d_ab   = symaddr(g_ab);
    float* d_h    = symaddr(g_h);

    // side streams + events (exist only at capture time; graph gets branches)
    cudaStream_t s1, s2;
    cudaStreamCreateWithFlags(&s1, cudaStreamNonBlocking);
    cudaStreamCreateWithFlags(&s2, cudaStreamNonBlocking);
    cudaEvent_t eF, e1, e2, eG, eQ;
    cudaEventCreateWithFlags(&eF, cudaEventDisableTiming);
    cudaEventCreateWithFlags(&e1, cudaEventDisableTiming);
    cudaEventCreateWithFlags(&e2, cudaEventDisableTiming);
    cudaEventCreateWithFlags(&eG, cudaEventDisableTiming);
    cudaEventCreateWithFlags(&eQ, cudaEventDisableTiming);

    // ---- fork ----
    cudaEventRecord(eF, 0);
    cudaStreamWaitEvent(s1, eF, 0);
    cudaStreamWaitEvent(s2, eF, 0);

    // s1: CSR construction chain (deg_zero also zeroes kinc/vinc)
    deg_zero<<<(DC * 128 + 255) / 256, 256, 0, s1>>>();
    deg_count<<<(EE + 255) / 256, 256, 0, s1>>>(adj);
    scan_offsets<<<1, 1024, 0, s1>>>();
    fill_csr<<<(EE + 255) / 256, 256, 0, s1>>>(adj);
    cudaEventRecord(e1, s1);

    // s2: rowsums, peq, fold (all independent)
    rowsums<<<(2 * DC * 32 + 255) / 256, 256, 0, s2>>>(Ek, Ev);
    sgemm2<0><<<dim3(1, 4), 256, 0, s2>>>(pos_emb, Wq, nullptr, nullptr, d_peq, 512, 128, 128);
    fold_woab<<<(128 * 128 + 255) / 256, 256, 0, s2>>>(Wo, tfa_W, tga_W, bo, tfa_b, tga_b);
    cudaEventRecord(e2, s2);

    // s0 spine: packs -> big GEMM
    pack_all<<<(PACK_TOTAL + 255) / 256, 256>>>(gcn_W, gcnA2_W, gcn_b, gcnA2_b,
                                                lin_W, tf_W, tg_W, tf_b, tg_b, Wq);
    mma_gemm<0, 0><<<dim3(4, 157), 256>>>(data_feature, d_W12t, nullptr, d_h,
                                          NN, 512, 512, nullptr, nullptr);

    // join CSR, then gather
    cudaStreamWaitEvent(0, e1, 0);
    gcn_gather<<<NN, 128>>>();
    cudaEventRecord(eG, 0);

    // s1 branch: lin -> q (independent of tftg chain)
    cudaStreamWaitEvent(s1, eG, 0);
    mma_gemm<1, 0><<<dim3(1, 157), 256, 0, s1>>>(d_g1, d_lint, lin_b, d_xg,
                                                 NN, 128, 256, nullptr, nullptr);
    mma_gemm<0, 0><<<dim3(1, 157), 256, 0, s1>>>(d_xg, d_Wqt, bq, d_q,
                                                 NN, 128, 128, nullptr, nullptr);
    cudaEventRecord(eQ, s1);

    // s0: tftg (+kin) -> splitk -> proj
    mma_gemm<1, 1><<<dim3(2, 157), 256>>>(d_xa, d_tftgt, d_btftg, d_tftg,
                                          NN, 256, 256, positions, pos_emb);
    splitk_ckv<<<dim3(2, 4, 50), 256>>>(Ek, Ev);
    cudaStreamWaitEvent(0, e2, 0);   // rowsums (proj), peq (attn), fold (ab)
    proj_ckv<<<dim3(1, 2, 2), 256>>>(Wk, bk, Wv, bv);

    // join q, then attention onward
    cudaStreamWaitEvent(0, eQ, 0);
    attn_kernel<<<dim3(157, 8), 128>>>(positions);
    mma_gemm<1, 0><<<dim3(1, 157), 256>>>(d_att, d_Woabt, d_bab2, d_ab,
                                          NN, 128, 128, nullptr, nullptr);
    norms_kernel<<<(NN + 255) / 256, 256>>>();
    final_pairs<<<(NT + 255) / 256, 256>>>(train_sample, (float*)d_out);

    cudaEventDestroy(eF); cudaEventDestroy(e1); cudaEventDestroy(e2);
    cudaEventDestroy(eG); cudaEventDestroy(eQ);
    cudaStreamDestroy(s1); cudaStreamDestroy(s2);
}